// round 1
// baseline (speedup 1.0000x reference)
#include <cuda_runtime.h>
#include <math.h>

#define BATCH 16
#define S1 61
#define SEQ 3721            // 61*61
#define DMODEL 128
#define HEADS 8
#define DH 16
#define NLAYER 4
#define FFDIM 512
#define PCH 49
#define MROWS (BATCH * SEQ) // 59536

// ---------------- scratch (device globals; no runtime allocation) ------------
__device__ float g_p[MROWS * PCH];
__device__ float g_h[MROWS * DMODEL];
__device__ float g_ln[MROWS * DMODEL];
__device__ float g_q[MROWS * DMODEL];
__device__ float g_k[MROWS * DMODEL];
__device__ float g_v[MROWS * DMODEL];
__device__ float g_att[MROWS * DMODEL];
__device__ float g_ff[MROWS * FFDIM];

// ---------------- conv 7x7 'same' + relu, out layout [B, S, 49] --------------
__global__ void conv_k(const float* __restrict__ x, const float* __restrict__ cw,
                       const float* __restrict__ cb, float* __restrict__ p) {
    int t = blockIdx.x * blockDim.x + threadIdx.x;
    if (t >= MROWS * PCH) return;
    int o = t % PCH;
    int s = (t / PCH) % SEQ;
    int b = t / (PCH * SEQ);
    int y = s / S1, xx = s % S1;
    const float* xb = x + (long)b * SEQ;
    const float* wo = cw + o * 49;
    float sum = cb[o];
#pragma unroll
    for (int dy = 0; dy < 7; dy++) {
        int iy = y + dy - 3;
        if (iy < 0 || iy >= S1) continue;
#pragma unroll
        for (int dx = 0; dx < 7; dx++) {
            int ix = xx + dx - 3;
            if (ix < 0 || ix >= S1) continue;
            sum += xb[iy * S1 + ix] * wo[dy * 7 + dx];
        }
    }
    p[t] = fmaxf(sum, 0.f);
}

// ---------------- generic tiled GEMM with fused epilogues --------------------
// C[M,N] = A[M,K] @ B[K,N]  (+ epilogue)
// EPI: 0 = none
//      2 = +bias +pos_table[row % SEQ]
//      3 = +bias +res (residual)
//      4 = gelu(acc + bias)  (exact erf)
#define BM 64
#define BN 64
#define BKK 16

template <int EPI>
__global__ void gemm_k(const float* __restrict__ A, const float* __restrict__ B,
                       const float* __restrict__ bias, const float* __restrict__ res,
                       const float* __restrict__ pos, float* __restrict__ C,
                       int M, int N, int K) {
    __shared__ float As[BKK][BM];
    __shared__ float Bs[BKK][BN];
    int tid = threadIdx.x;
    int tx = tid & 15, ty = tid >> 4;
    int m0 = blockIdx.y * BM, n0 = blockIdx.x * BN;
    int ar = tid >> 2, ac4 = (tid & 3) * 4;       // A tile loader: row 0..63, col group
    int bc = tid >> 4, bn4 = (tid & 15) * 4;      // B tile loader: row 0..15, col group
    float acc[4][4] = {};

    for (int k0 = 0; k0 < K; k0 += BKK) {
        int arow = m0 + ar;
#pragma unroll
        for (int u = 0; u < 4; u++) {
            int c = ac4 + u;
            float val = 0.f;
            if (arow < M && (k0 + c) < K) val = A[(long)arow * K + k0 + c];
            As[c][ar] = val;
        }
        {
            float4 val = make_float4(0.f, 0.f, 0.f, 0.f);
            if (k0 + bc < K) val = *(const float4*)&B[(long)(k0 + bc) * N + n0 + bn4];
            *(float4*)&Bs[bc][bn4] = val;
        }
        __syncthreads();
#pragma unroll
        for (int kk = 0; kk < BKK; kk++) {
            float4 a = *(float4*)&As[kk][ty * 4];
            float4 b = *(float4*)&Bs[kk][tx * 4];
            float av[4] = {a.x, a.y, a.z, a.w};
            float bv[4] = {b.x, b.y, b.z, b.w};
#pragma unroll
            for (int i = 0; i < 4; i++)
#pragma unroll
                for (int j = 0; j < 4; j++) acc[i][j] += av[i] * bv[j];
        }
        __syncthreads();
    }

#pragma unroll
    for (int i = 0; i < 4; i++) {
        int row = m0 + ty * 4 + i;
        if (row >= M) continue;
#pragma unroll
        for (int j = 0; j < 4; j++) {
            int col = n0 + tx * 4 + j;
            float v = acc[i][j];
            if (EPI >= 2) v += bias[col];
            if (EPI == 2) v += pos[(long)(row % SEQ) * DMODEL + col];
            if (EPI == 3) v += res[(long)row * N + col];
            if (EPI == 4) v = 0.5f * v * (1.f + erff(v * 0.70710678118654752f));
            C[(long)row * N + col] = v;
        }
    }
}

// ---------------- layernorm: warp per row, float4 ----------------------------
__global__ void ln_k(const float* __restrict__ x, const float* __restrict__ sc,
                     const float* __restrict__ bi, float* __restrict__ o, int M) {
    int warp = (blockIdx.x * blockDim.x + threadIdx.x) >> 5;
    int lane = threadIdx.x & 31;
    if (warp >= M) return;
    float4 v = ((const float4*)(x + (long)warp * DMODEL))[lane];
    float sum = v.x + v.y + v.z + v.w;
#pragma unroll
    for (int off = 16; off; off >>= 1) sum += __shfl_xor_sync(~0u, sum, off);
    float mean = sum * (1.f / 128.f);
    float dx = v.x - mean, dy = v.y - mean, dz = v.z - mean, dw = v.w - mean;
    float vs = dx * dx + dy * dy + dz * dz + dw * dw;
#pragma unroll
    for (int off = 16; off; off >>= 1) vs += __shfl_xor_sync(~0u, vs, off);
    float inv = rsqrtf(vs * (1.f / 128.f) + 1e-5f);
    float4 s4 = ((const float4*)sc)[lane];
    float4 b4 = ((const float4*)bi)[lane];
    float4 ov = make_float4(dx * inv * s4.x + b4.x, dy * inv * s4.y + b4.y,
                            dz * inv * s4.z + b4.z, dw * inv * s4.w + b4.w);
    ((float4*)(o + (long)warp * DMODEL))[lane] = ov;
}

// ---------------- local windowed attention -----------------------------------
// block = (window w, batch*head). warp-per-query, 2-pass softmax.
__global__ void attn_k(const float* __restrict__ q, const float* __restrict__ k,
                       const float* __restrict__ v, float* __restrict__ o) {
    __shared__ float qs[S1][17];
    __shared__ float ks[3 * S1][17];
    __shared__ float vs[3 * S1][17];
    int w = blockIdx.x;
    int bh = blockIdx.y;
    int b = bh >> 3, h = bh & 7;
    int tid = threadIdx.x;
    int jstart = (w > 0) ? 0 : S1;
    int jend = (w < S1 - 1) ? 3 * S1 : 2 * S1;
    long base = (long)b * SEQ * DMODEL + h * DH;

    for (int idx = tid; idx < S1 * DH; idx += blockDim.x) {
        int i = idx >> 4, d = idx & 15;
        qs[i][d] = q[base + (long)(w * S1 + i) * DMODEL + d] * 0.25f; // DH^-0.5
    }
    int cnt = jend - jstart;
    for (int idx = tid; idx < cnt * DH; idx += blockDim.x) {
        int j = jstart + (idx >> 4), d = idx & 15;
        long s = (long)((w - 1) * S1 + j);
        ks[j][d] = k[base + s * DMODEL + d];
        vs[j][d] = v[base + s * DMODEL + d];
    }
    __syncthreads();

    int warp = tid >> 5, lane = tid & 31;
    for (int i = warp; i < S1; i += 8) {
        float ql[DH];
#pragma unroll
        for (int d = 0; d < DH; d++) ql[d] = qs[i][d];
        float sc[6];
        float mx = -1e30f;
        int c = 0;
        for (int j = jstart + lane; j < jend; j += 32) {
            float s = 0.f;
#pragma unroll
            for (int d = 0; d < DH; d++) s += ql[d] * ks[j][d];
            sc[c++] = s;
            mx = fmaxf(mx, s);
        }
#pragma unroll
        for (int off = 16; off; off >>= 1) mx = fmaxf(mx, __shfl_xor_sync(~0u, mx, off));
        float se = 0.f;
        float acc[DH] = {};
        c = 0;
        for (int j = jstart + lane; j < jend; j += 32) {
            float p = __expf(sc[c++] - mx);
            se += p;
#pragma unroll
            for (int d = 0; d < DH; d++) acc[d] += p * vs[j][d];
        }
#pragma unroll
        for (int off = 16; off; off >>= 1) se += __shfl_xor_sync(~0u, se, off);
#pragma unroll
        for (int d = 0; d < DH; d++) {
#pragma unroll
            for (int off = 16; off; off >>= 1) acc[d] += __shfl_xor_sync(~0u, acc[d], off);
        }
        if (lane == 0) {
            float inv = 1.f / se;
            long orow = base + (long)(w * S1 + i) * DMODEL;
#pragma unroll
            for (int d = 0; d < DH; d++) o[orow + d] = acc[d] * inv;
        }
    }
}

// ---------------- fused output head: relu(h@W1+b1)@w2+b2 ---------------------
__global__ void head_k(const float* __restrict__ h, const float* __restrict__ w1,
                       const float* __restrict__ b1, const float* __restrict__ w2,
                       const float* __restrict__ b2, float* __restrict__ out) {
    __shared__ float hr[DMODEL];
    __shared__ float red[4];
    int row = blockIdx.x;
    int tid = threadIdx.x;
    hr[tid] = h[(long)row * DMODEL + tid];
    __syncthreads();
    float s = 0.f;
#pragma unroll 8
    for (int kk = 0; kk < DMODEL; kk++) s += hr[kk] * w1[kk * DMODEL + tid];
    s = fmaxf(s + b1[tid], 0.f) * w2[tid];
#pragma unroll
    for (int off = 16; off; off >>= 1) s += __shfl_xor_sync(~0u, s, off);
    if ((tid & 31) == 0) red[tid >> 5] = s;
    __syncthreads();
    if (tid == 0) out[row] = red[0] + red[1] + red[2] + red[3] + b2[0];
}

// ---------------- launch -------------------------------------------------------
extern "C" void kernel_launch(void* const* d_in, const int* in_sizes, int n_in,
                              void* d_out, int out_size) {
    const float* x       = (const float*)d_in[0];
    const float* conv_w  = (const float*)d_in[1];
    const float* conv_b  = (const float*)d_in[2];
    const float* lt_w    = (const float*)d_in[3];
    const float* lt_b    = (const float*)d_in[4];
    const float* pos     = (const float*)d_in[5];
    const float* ln1_s   = (const float*)d_in[6];
    const float* ln1_b   = (const float*)d_in[7];
    const float* wq      = (const float*)d_in[8];
    const float* wk      = (const float*)d_in[9];
    const float* wv      = (const float*)d_in[10];
    const float* wo      = (const float*)d_in[11];
    const float* wo_b    = (const float*)d_in[12];
    const float* ln2_s   = (const float*)d_in[13];
    const float* ln2_b   = (const float*)d_in[14];
    const float* ff_w1   = (const float*)d_in[15];
    const float* ff_b1   = (const float*)d_in[16];
    const float* ff_w2   = (const float*)d_in[17];
    const float* ff_b2   = (const float*)d_in[18];
    const float* pre_w1  = (const float*)d_in[19];
    const float* pre_b1  = (const float*)d_in[20];
    const float* pre_w2  = (const float*)d_in[21];
    const float* pre_b2  = (const float*)d_in[22];
    float* out = (float*)d_out;

    float *p, *h, *ln, *q, *k, *v, *att, *ff;
    cudaGetSymbolAddress((void**)&p,   g_p);
    cudaGetSymbolAddress((void**)&h,   g_h);
    cudaGetSymbolAddress((void**)&ln,  g_ln);
    cudaGetSymbolAddress((void**)&q,   g_q);
    cudaGetSymbolAddress((void**)&k,   g_k);
    cudaGetSymbolAddress((void**)&v,   g_v);
    cudaGetSymbolAddress((void**)&att, g_att);
    cudaGetSymbolAddress((void**)&ff,  g_ff);

    const int M = MROWS;
    dim3 gD(DMODEL / BN, (M + BM - 1) / BM);     // N=128 GEMMs
    dim3 gF(FFDIM / BN, (M + BM - 1) / BM);      // N=512 GEMM
    int lnGrid = (M + 7) / 8;

    // conv + embed (+pos)
    conv_k<<<(MROWS * PCH + 255) / 256, 256>>>(x, conv_w, conv_b, p);
    gemm_k<2><<<gD, 256>>>(p, lt_w, lt_b, nullptr, pos, h, M, DMODEL, PCH);

    for (int i = 0; i < NLAYER; i++) {
        const float* wqi = wq + (long)i * DMODEL * DMODEL;
        const float* wki = wk + (long)i * DMODEL * DMODEL;
        const float* wvi = wv + (long)i * DMODEL * DMODEL;
        const float* woi = wo + (long)i * DMODEL * DMODEL;

        ln_k<<<lnGrid, 256>>>(h, ln1_s + i * DMODEL, ln1_b + i * DMODEL, ln, M);
        gemm_k<0><<<gD, 256>>>(ln, wqi, nullptr, nullptr, nullptr, q, M, DMODEL, DMODEL);
        gemm_k<0><<<gD, 256>>>(ln, wki, nullptr, nullptr, nullptr, k, M, DMODEL, DMODEL);
        gemm_k<0><<<gD, 256>>>(ln, wvi, nullptr, nullptr, nullptr, v, M, DMODEL, DMODEL);
        attn_k<<<dim3(S1, BATCH * HEADS), 256>>>(q, k, v, att);
        gemm_k<3><<<gD, 256>>>(att, woi, wo_b + i * DMODEL, h, nullptr, h, M, DMODEL, DMODEL);

        ln_k<<<lnGrid, 256>>>(h, ln2_s + i * DMODEL, ln2_b + i * DMODEL, ln, M);
        gemm_k<4><<<gF, 256>>>(ln, ff_w1 + (long)i * DMODEL * FFDIM, ff_b1 + i * FFDIM,
                               nullptr, nullptr, ff, M, FFDIM, DMODEL);
        gemm_k<3><<<gD, 256>>>(ff, ff_w2 + (long)i * FFDIM * DMODEL, ff_b2 + i * DMODEL,
                               h, nullptr, h, M, DMODEL, FFDIM);
    }

    head_k<<<M, DMODEL>>>(h, pre_w1, pre_b1, pre_w2, pre_b2, out);
}

// round 3
// speedup vs baseline: 1.2607x; 1.2607x over previous
#include <cuda_runtime.h>
#include <cuda_bf16.h>
#include <cstdint>
#include <math.h>

#define BATCH 16
#define S1 61
#define SEQ 3721
#define DMODEL 128
#define HEADS 8
#define DH 16
#define NLAYER 4
#define FFDIM 512
#define PCH 49
#define MROWS (BATCH * SEQ) // 59536
#define MTILES ((MROWS + 127) / 128) // 466

// ---------------------------------------------------------------- scratch
__device__ __nv_bfloat16 g_phi[MROWS * 64],  g_plo[MROWS * 64];
__device__ float         g_h[MROWS * 128];
__device__ __nv_bfloat16 g_lnhi[MROWS * 128], g_lnlo[MROWS * 128];
__device__ float         g_qkv[(size_t)MROWS * 384];
__device__ __nv_bfloat16 g_atthi[MROWS * 128], g_attlo[MROWS * 128];
__device__ __nv_bfloat16 g_ffhi[(size_t)MROWS * 512], g_fflo[(size_t)MROWS * 512];
__device__ __nv_bfloat16 g_hhi[MROWS * 128], g_hlo[MROWS * 128];
__device__ __nv_bfloat16 g_wlt_h[128 * 64],  g_wlt_l[128 * 64];
__device__ __nv_bfloat16 g_wqkv_h[NLAYER * 384 * 128], g_wqkv_l[NLAYER * 384 * 128];
__device__ __nv_bfloat16 g_wo_h[NLAYER * 128 * 128],   g_wo_l[NLAYER * 128 * 128];
__device__ __nv_bfloat16 g_wf1_h[NLAYER * 512 * 128],  g_wf1_l[NLAYER * 512 * 128];
__device__ __nv_bfloat16 g_wf2_h[NLAYER * 128 * 512],  g_wf2_l[NLAYER * 128 * 512];
__device__ __nv_bfloat16 g_wp1_h[128 * 128],  g_wp1_l[128 * 128];

// ---------------------------------------------------------------- helpers
__device__ __forceinline__ uint32_t smem_u32(const void* p) {
    uint32_t a;
    asm("{ .reg .u64 t; cvta.to.shared.u64 t, %1; cvt.u32.u64 %0, t; }" : "=r"(a) : "l"(p));
    return a;
}
__device__ __forceinline__ void ldsm4(uint32_t* r, uint32_t addr) {
    asm volatile("ldmatrix.sync.aligned.m8n8.x4.shared.b16 {%0,%1,%2,%3}, [%4];"
                 : "=r"(r[0]), "=r"(r[1]), "=r"(r[2]), "=r"(r[3]) : "r"(addr));
}
__device__ __forceinline__ void mma16816(float* c, const uint32_t* a, uint32_t b0, uint32_t b1) {
    asm volatile("mma.sync.aligned.m16n8k16.row.col.f32.bf16.bf16.f32 "
                 "{%0,%1,%2,%3}, {%4,%5,%6,%7}, {%8,%9}, {%0,%1,%2,%3};"
                 : "+f"(c[0]), "+f"(c[1]), "+f"(c[2]), "+f"(c[3])
                 : "r"(a[0]), "r"(a[1]), "r"(a[2]), "r"(a[3]), "r"(b0), "r"(b1));
}

// ------------------------------------------- weight transpose + hi/lo split
// W[K,N] fp32 -> Wt[N,Kp] bf16 hi/lo (zero pad K..Kp)
__global__ void wprep_k(const float* __restrict__ W, __nv_bfloat16* __restrict__ hi,
                        __nv_bfloat16* __restrict__ lo, int K, int N, int Kp) {
    int t = blockIdx.x * blockDim.x + threadIdx.x;
    if (t >= N * Kp) return;
    int n = t / Kp, kk = t % Kp;
    float v = (kk < K) ? W[(long)kk * N + n] : 0.f;
    __nv_bfloat16 h = __float2bfloat16(v);
    hi[t] = h;
    lo[t] = __float2bfloat16(v - __bfloat162float(h));
}

// ---------------- conv 7x7 'same' + relu -> bf16 hi/lo [M,64] ----------------
__global__ void conv_k(const float* __restrict__ x, const float* __restrict__ cw,
                       const float* __restrict__ cb, __nv_bfloat16* __restrict__ phi,
                       __nv_bfloat16* __restrict__ plo) {
    int t = blockIdx.x * blockDim.x + threadIdx.x;
    if (t >= MROWS * 64) return;
    int o = t & 63;
    float sum = 0.f;
    if (o < PCH) {
        int s = (t >> 6) % SEQ;
        int b = (t >> 6) / SEQ;
        int y = s / S1, xx = s % S1;
        const float* xb = x + (long)b * SEQ;
        const float* wo = cw + o * 49;
        sum = cb[o];
#pragma unroll
        for (int dy = 0; dy < 7; dy++) {
            int iy = y + dy - 3;
            if (iy < 0 || iy >= S1) continue;
#pragma unroll
            for (int dx = 0; dx < 7; dx++) {
                int ix = xx + dx - 3;
                if (ix < 0 || ix >= S1) continue;
                sum += xb[iy * S1 + ix] * wo[dy * 7 + dx];
            }
        }
        sum = fmaxf(sum, 0.f);
    }
    __nv_bfloat16 h = __float2bfloat16(sum);
    phi[t] = h;
    plo[t] = __float2bfloat16(sum - __bfloat162float(h));
}

// ---------------- layernorm: warp per row -> bf16 hi/lo ----------------------
__global__ void ln_k(const float* __restrict__ x, const float* __restrict__ sc,
                     const float* __restrict__ bi, __nv_bfloat16* __restrict__ ohi,
                     __nv_bfloat16* __restrict__ olo, int M) {
    int warp = (blockIdx.x * blockDim.x + threadIdx.x) >> 5;
    int lane = threadIdx.x & 31;
    if (warp >= M) return;
    float4 v = ((const float4*)(x + (long)warp * DMODEL))[lane];
    float sum = v.x + v.y + v.z + v.w;
#pragma unroll
    for (int off = 16; off; off >>= 1) sum += __shfl_xor_sync(~0u, sum, off);
    float mean = sum * (1.f / 128.f);
    float dx = v.x - mean, dy = v.y - mean, dz = v.z - mean, dw = v.w - mean;
    float vs = dx * dx + dy * dy + dz * dz + dw * dw;
#pragma unroll
    for (int off = 16; off; off >>= 1) vs += __shfl_xor_sync(~0u, vs, off);
    float inv = rsqrtf(vs * (1.f / 128.f) + 1e-5f);
    float4 s4 = ((const float4*)sc)[lane];
    float4 b4 = ((const float4*)bi)[lane];
    float o[4] = {dx * inv * s4.x + b4.x, dy * inv * s4.y + b4.y,
                  dz * inv * s4.z + b4.z, dw * inv * s4.w + b4.w};
    __nv_bfloat16 hv[4], lv[4];
#pragma unroll
    for (int i = 0; i < 4; i++) {
        hv[i] = __float2bfloat16(o[i]);
        lv[i] = __float2bfloat16(o[i] - __bfloat162float(hv[i]));
    }
    *(uint2*)(ohi + (long)warp * 128 + lane * 4) = *(uint2*)hv;
    *(uint2*)(olo + (long)warp * 128 + lane * 4) = *(uint2*)lv;
}

// ---------------- mma.sync GEMM with 3-MMA fp32 emulation --------------------
// C[M,N] = A[M,K] @ Bt[N,K]^T; A,B as bf16 hi/lo pairs; CTA tile 128x128.
// EPI: 0 fp32 C; 2 +bias+pos; 3 +bias+res (fp32, optional hi/lo);
//      4 gelu(+bias)->hi/lo; 5 head: C[row]=sum relu(acc+bias)*w2 + pos[0]
#define TILE_B 16384u
#define SMEMSZ (4 * 16384)

template <int EPI>
__global__ void __launch_bounds__(256, 2)
tgemm(const __nv_bfloat16* __restrict__ Ah, const __nv_bfloat16* __restrict__ Al,
      const __nv_bfloat16* __restrict__ Bh, const __nv_bfloat16* __restrict__ Bl,
      const float* __restrict__ bias, const float* __restrict__ res,
      const float* __restrict__ pos, const float* __restrict__ w2,
      float* __restrict__ C, __nv_bfloat16* __restrict__ Chi,
      __nv_bfloat16* __restrict__ Clo, int M, int N, int K) {
    extern __shared__ char sm[];
    __shared__ float red[2][128];
    uint32_t sb = smem_u32(sm);
    int tid = threadIdx.x;
    int w = tid >> 5, lane = tid & 31;
    int wm = w & 3, wn = w >> 2;
    int m0 = blockIdx.y * 128, n0 = blockIdx.x * 128;
    int nk = K >> 6;

    float acc[2][8][4];
#pragma unroll
    for (int i = 0; i < 2; i++)
#pragma unroll
        for (int j = 0; j < 8; j++)
#pragma unroll
            for (int q = 0; q < 4; q++) acc[i][j][q] = 0.f;

    // per-thread ldmatrix row bases (fixed)
    int rA[2], rB[4];
#pragma unroll
    for (int mi = 0; mi < 2; mi++) rA[mi] = wm * 32 + mi * 16 + (lane & 15);
#pragma unroll
    for (int ng = 0; ng < 4; ng++)
        rB[ng] = wn * 64 + ng * 16 + ((lane >> 4) << 3) + (lane & 7);
    int cA = lane >> 4;          // chunk offset for A
    int cB = (lane >> 3) & 1;    // chunk offset for B

    for (int c = 0; c < nk; c++) {
        // ---- load 4 tiles (Ah,Al,Bh,Bl): 128 rows x 64 bf16, XOR-swizzled ----
#pragma unroll
        for (int it = 0; it < 16; it++) {
            int slot = it * 256 + tid;
            int t = it >> 2;                 // tile id 0..3 (uniform)
            int row = (slot >> 3) & 127;
            int chunk = slot & 7;
            const __nv_bfloat16* src = (t == 0) ? Ah : (t == 1) ? Al : (t == 2) ? Bh : Bl;
            long grow = (t < 2) ? (long)(m0 + row) : (long)(n0 + row);
            bool ok = (t < 2) ? (m0 + row < M) : true;
            uint4 val = make_uint4(0, 0, 0, 0);
            if (ok) val = *(const uint4*)(src + grow * K + ((long)c << 6) + chunk * 8);
            *(uint4*)(sm + (uint32_t)t * TILE_B + row * 128 + ((chunk ^ (row & 7)) << 4)) = val;
        }
        __syncthreads();

        // ---- 3 combos: (Ah,Bh), (Al,Bh), (Ah,Bl) ----
#pragma unroll
        for (int combo = 0; combo < 3; combo++) {
            uint32_t aT = sb + ((combo == 1) ? 1u : 0u) * TILE_B;
            uint32_t bT = sb + ((combo == 2) ? 3u : 2u) * TILE_B;
#pragma unroll
            for (int ks = 0; ks < 4; ks++) {
                int kc = ks * 2;
                uint32_t a[2][4];
#pragma unroll
                for (int mi = 0; mi < 2; mi++) {
                    int row = rA[mi];
                    ldsm4(a[mi], aT + row * 128 + (((kc + cA) ^ (row & 7)) << 4));
                }
#pragma unroll
                for (int ng = 0; ng < 4; ng++) {
                    int row = rB[ng];
                    uint32_t b[4];
                    ldsm4(b, bT + row * 128 + (((kc + cB) ^ (row & 7)) << 4));
#pragma unroll
                    for (int mi = 0; mi < 2; mi++) {
                        mma16816(acc[mi][ng * 2], a[mi], b[0], b[1]);
                        mma16816(acc[mi][ng * 2 + 1], a[mi], b[2], b[3]);
                    }
                }
            }
        }
        __syncthreads();
    }

    // ---------------- epilogue ----------------
    int tg = lane >> 2;       // 0..7 row group
    int tc = (lane & 3) * 2;  // col pair
    if (EPI == 5) {
        float p[2][2] = {};
#pragma unroll
        for (int mi = 0; mi < 2; mi++)
#pragma unroll
            for (int ni = 0; ni < 8; ni++) {
                int col = wn * 64 + ni * 8 + tc;
                float b0 = bias[col], b1 = bias[col + 1];
                float w20 = w2[col], w21 = w2[col + 1];
                p[mi][0] += fmaxf(acc[mi][ni][0] + b0, 0.f) * w20 +
                            fmaxf(acc[mi][ni][1] + b1, 0.f) * w21;
                p[mi][1] += fmaxf(acc[mi][ni][2] + b0, 0.f) * w20 +
                            fmaxf(acc[mi][ni][3] + b1, 0.f) * w21;
            }
#pragma unroll
        for (int mi = 0; mi < 2; mi++)
#pragma unroll
            for (int hf = 0; hf < 2; hf++) {
                float v = p[mi][hf];
                v += __shfl_xor_sync(~0u, v, 1);
                v += __shfl_xor_sync(~0u, v, 2);
                if ((lane & 3) == 0) red[wn][wm * 32 + mi * 16 + hf * 8 + tg] = v;
            }
        __syncthreads();
        if (tid < 128) {
            int row = m0 + tid;
            if (row < M) C[row] = red[0][tid] + red[1][tid] + pos[0];
        }
        return;
    }

#pragma unroll
    for (int mi = 0; mi < 2; mi++) {
#pragma unroll
        for (int hf = 0; hf < 2; hf++) {
            int row = m0 + wm * 32 + mi * 16 + hf * 8 + tg;
            if (row >= M) continue;
#pragma unroll
            for (int ni = 0; ni < 8; ni++) {
                int col = n0 + wn * 64 + ni * 8 + tc;
                float v0 = acc[mi][ni][hf * 2 + 0];
                float v1 = acc[mi][ni][hf * 2 + 1];
                if (EPI == 0) {
                    *(float2*)&C[(long)row * N + col] = make_float2(v0, v1);
                } else if (EPI == 2) {
                    long pr = (long)(row % SEQ) * 128 + col;
                    v0 += bias[col] + pos[pr];
                    v1 += bias[col + 1] + pos[pr + 1];
                    *(float2*)&C[(long)row * N + col] = make_float2(v0, v1);
                } else if (EPI == 3) {
                    v0 += bias[col] + res[(long)row * N + col];
                    v1 += bias[col + 1] + res[(long)row * N + col + 1];
                    *(float2*)&C[(long)row * N + col] = make_float2(v0, v1);
                    if (Chi) {
                        __nv_bfloat16 h0 = __float2bfloat16(v0), h1 = __float2bfloat16(v1);
                        __nv_bfloat16 hl[2] = {h0, h1};
                        __nv_bfloat16 ll[2] = {__float2bfloat16(v0 - __bfloat162float(h0)),
                                               __float2bfloat16(v1 - __bfloat162float(h1))};
                        *(uint32_t*)&Chi[(long)row * N + col] = *(uint32_t*)hl;
                        *(uint32_t*)&Clo[(long)row * N + col] = *(uint32_t*)ll;
                    }
                } else { // EPI 4: gelu -> hi/lo
                    v0 += bias[col];
                    v1 += bias[col + 1];
                    v0 = 0.5f * v0 * (1.f + erff(v0 * 0.70710678118654752f));
                    v1 = 0.5f * v1 * (1.f + erff(v1 * 0.70710678118654752f));
                    __nv_bfloat16 h0 = __float2bfloat16(v0), h1 = __float2bfloat16(v1);
                    __nv_bfloat16 hl[2] = {h0, h1};
                    __nv_bfloat16 ll[2] = {__float2bfloat16(v0 - __bfloat162float(h0)),
                                           __float2bfloat16(v1 - __bfloat162float(h1))};
                    *(uint32_t*)&Chi[(long)row * N + col] = *(uint32_t*)hl;
                    *(uint32_t*)&Clo[(long)row * N + col] = *(uint32_t*)ll;
                }
            }
        }
    }
}

// ---------------- local windowed attention -----------------------------------
__global__ void attn_k(const float* __restrict__ qkv, __nv_bfloat16* __restrict__ ohi,
                       __nv_bfloat16* __restrict__ olo) {
    __shared__ float qs[S1][17];
    __shared__ float ks[3 * S1][17];
    __shared__ float vs[3 * S1][17];
    __shared__ float ps[8][192];
    int w = blockIdx.x;
    int bh = blockIdx.y;
    int b = bh >> 3, h = bh & 7;
    int tid = threadIdx.x;
    int jstart = (w > 0) ? 0 : S1;
    int jend = (w < S1 - 1) ? 3 * S1 : 2 * S1;
    long rb = (long)b * SEQ;

    for (int idx = tid; idx < S1 * DH; idx += 256) {
        int i = idx >> 4, d = idx & 15;
        qs[i][d] = qkv[(rb + w * S1 + i) * 384 + h * 16 + d] * 0.25f;
    }
    int cnt = jend - jstart;
    for (int idx = tid; idx < cnt * DH; idx += 256) {
        int j = jstart + (idx >> 4), d = idx & 15;
        long r = rb + (long)(w - 1) * S1 + j;
        ks[j][d] = qkv[r * 384 + 128 + h * 16 + d];
        vs[j][d] = qkv[r * 384 + 256 + h * 16 + d];
    }
    __syncthreads();

    int warp = tid >> 5, lane = tid & 31;
    for (int i = warp; i < S1; i += 8) {
        float ql[DH];
#pragma unroll
        for (int d = 0; d < DH; d++) ql[d] = qs[i][d];
        float sc[6];
        float mx = -1e30f;
        int c = 0;
        for (int j = jstart + lane; j < jend; j += 32) {
            float s = 0.f;
#pragma unroll
            for (int d = 0; d < DH; d++) s += ql[d] * ks[j][d];
            sc[c++] = s;
            mx = fmaxf(mx, s);
        }
#pragma unroll
        for (int off = 16; off; off >>= 1) mx = fmaxf(mx, __shfl_xor_sync(~0u, mx, off));
        float se = 0.f;
        c = 0;
        for (int j = jstart + lane; j < jend; j += 32) {
            float p = __expf(sc[c] - mx);
            sc[c++] = p;
            se += p;
        }
#pragma unroll
        for (int off = 16; off; off >>= 1) se += __shfl_xor_sync(~0u, se, off);
        float inv = 1.f / se;
        c = 0;
        for (int j = jstart + lane; j < jend; j += 32) ps[warp][j - jstart] = sc[c++] * inv;
        __syncwarp();
        int d = lane & 15, half = lane >> 4;
        float accv = 0.f;
        for (int jj = half; jj < cnt; jj += 2) accv += ps[warp][jj] * vs[jstart + jj][d];
        accv += __shfl_xor_sync(~0u, accv, 16);
        if (lane < 16) {
            long orow = (rb + w * S1 + i) * 128 + h * 16 + d;
            __nv_bfloat16 hv = __float2bfloat16(accv);
            ohi[orow] = hv;
            olo[orow] = __float2bfloat16(accv - __bfloat162float(hv));
        }
        __syncwarp();
    }
}

// ---------------- launch ------------------------------------------------------
extern "C" void kernel_launch(void* const* d_in, const int* in_sizes, int n_in,
                              void* d_out, int out_size) {
    const float* x      = (const float*)d_in[0];
    const float* conv_w = (const float*)d_in[1];
    const float* conv_b = (const float*)d_in[2];
    const float* lt_w   = (const float*)d_in[3];
    const float* lt_b   = (const float*)d_in[4];
    const float* pos    = (const float*)d_in[5];
    const float* ln1_s  = (const float*)d_in[6];
    const float* ln1_b  = (const float*)d_in[7];
    const float* wq     = (const float*)d_in[8];
    const float* wk     = (const float*)d_in[9];
    const float* wv     = (const float*)d_in[10];
    const float* wo     = (const float*)d_in[11];
    const float* wo_b   = (const float*)d_in[12];
    const float* ln2_s  = (const float*)d_in[13];
    const float* ln2_b  = (const float*)d_in[14];
    const float* ff_w1  = (const float*)d_in[15];
    const float* ff_b1  = (const float*)d_in[16];
    const float* ff_w2  = (const float*)d_in[17];
    const float* ff_b2  = (const float*)d_in[18];
    const float* pre_w1 = (const float*)d_in[19];
    const float* pre_b1 = (const float*)d_in[20];
    const float* pre_w2 = (const float*)d_in[21];
    const float* pre_b2 = (const float*)d_in[22];
    float* out = (float*)d_out;

    static bool attr_done = false;
    if (!attr_done) {
        cudaFuncSetAttribute(tgemm<0>, cudaFuncAttributeMaxDynamicSharedMemorySize, SMEMSZ);
        cudaFuncSetAttribute(tgemm<2>, cudaFuncAttributeMaxDynamicSharedMemorySize, SMEMSZ);
        cudaFuncSetAttribute(tgemm<3>, cudaFuncAttributeMaxDynamicSharedMemorySize, SMEMSZ);
        cudaFuncSetAttribute(tgemm<4>, cudaFuncAttributeMaxDynamicSharedMemorySize, SMEMSZ);
        cudaFuncSetAttribute(tgemm<5>, cudaFuncAttributeMaxDynamicSharedMemorySize, SMEMSZ);
        attr_done = true;
    }

    __nv_bfloat16 *phi, *plo, *lnhi, *lnlo, *atthi, *attlo, *ffhi, *fflo, *hhi, *hlo;
    __nv_bfloat16 *wlt_h, *wlt_l, *wqkv_h, *wqkv_l, *wo_h, *wo_l, *wf1_h, *wf1_l, *wf2_h, *wf2_l, *wp1_h, *wp1_l;
    float *h, *qkv;
    cudaGetSymbolAddress((void**)&phi, g_phi);     cudaGetSymbolAddress((void**)&plo, g_plo);
    cudaGetSymbolAddress((void**)&h, g_h);         cudaGetSymbolAddress((void**)&qkv, g_qkv);
    cudaGetSymbolAddress((void**)&lnhi, g_lnhi);   cudaGetSymbolAddress((void**)&lnlo, g_lnlo);
    cudaGetSymbolAddress((void**)&atthi, g_atthi); cudaGetSymbolAddress((void**)&attlo, g_attlo);
    cudaGetSymbolAddress((void**)&ffhi, g_ffhi);   cudaGetSymbolAddress((void**)&fflo, g_fflo);
    cudaGetSymbolAddress((void**)&hhi, g_hhi);     cudaGetSymbolAddress((void**)&hlo, g_hlo);
    cudaGetSymbolAddress((void**)&wlt_h, g_wlt_h); cudaGetSymbolAddress((void**)&wlt_l, g_wlt_l);
    cudaGetSymbolAddress((void**)&wqkv_h, g_wqkv_h); cudaGetSymbolAddress((void**)&wqkv_l, g_wqkv_l);
    cudaGetSymbolAddress((void**)&wo_h, g_wo_h);   cudaGetSymbolAddress((void**)&wo_l, g_wo_l);
    cudaGetSymbolAddress((void**)&wf1_h, g_wf1_h); cudaGetSymbolAddress((void**)&wf1_l, g_wf1_l);
    cudaGetSymbolAddress((void**)&wf2_h, g_wf2_h); cudaGetSymbolAddress((void**)&wf2_l, g_wf2_l);
    cudaGetSymbolAddress((void**)&wp1_h, g_wp1_h); cudaGetSymbolAddress((void**)&wp1_l, g_wp1_l);

    // ---- weight prep (transpose + hi/lo split) ----
    auto wp = [&](const float* W, __nv_bfloat16* hi, __nv_bfloat16* lo, int K, int N, int Kp) {
        int n = N * Kp;
        wprep_k<<<(n + 255) / 256, 256>>>(W, hi, lo, K, N, Kp);
    };
    wp(lt_w, wlt_h, wlt_l, 49, 128, 64);
    wp(pre_w1, wp1_h, wp1_l, 128, 128, 128);
    for (int i = 0; i < NLAYER; i++) {
        wp(wq + (long)i * 16384, wqkv_h + (long)i * 384 * 128, wqkv_l + (long)i * 384 * 128, 128, 128, 128);
        wp(wk + (long)i * 16384, wqkv_h + (long)i * 384 * 128 + 128 * 128, wqkv_l + (long)i * 384 * 128 + 128 * 128, 128, 128, 128);
        wp(wv + (long)i * 16384, wqkv_h + (long)i * 384 * 128 + 256 * 128, wqkv_l + (long)i * 384 * 128 + 256 * 128, 128, 128, 128);
        wp(wo + (long)i * 16384, wo_h + (long)i * 16384, wo_l + (long)i * 16384, 128, 128, 128);
        wp(ff_w1 + (long)i * 128 * 512, wf1_h + (long)i * 512 * 128, wf1_l + (long)i * 512 * 128, 128, 512, 128);
        wp(ff_w2 + (long)i * 512 * 128, wf2_h + (long)i * 128 * 512, wf2_l + (long)i * 128 * 512, 512, 128, 512);
    }

    const int M = MROWS;
    int lnGrid = (M + 7) / 8;

    conv_k<<<(MROWS * 64 + 255) / 256, 256>>>(x, conv_w, conv_b, phi, plo);
    tgemm<2><<<dim3(1, MTILES), 256, SMEMSZ>>>(phi, plo, wlt_h, wlt_l, lt_b, nullptr, pos,
                                               nullptr, h, nullptr, nullptr, M, 128, 64);

    for (int i = 0; i < NLAYER; i++) {
        ln_k<<<lnGrid, 256>>>(h, ln1_s + i * 128, ln1_b + i * 128, lnhi, lnlo, M);
        tgemm<0><<<dim3(3, MTILES), 256, SMEMSZ>>>(lnhi, lnlo,
            wqkv_h + (long)i * 384 * 128, wqkv_l + (long)i * 384 * 128,
            nullptr, nullptr, nullptr, nullptr, qkv, nullptr, nullptr, M, 384, 128);
        attn_k<<<dim3(S1, BATCH * HEADS), 256>>>(qkv, atthi, attlo);
        tgemm<3><<<dim3(1, MTILES), 256, SMEMSZ>>>(atthi, attlo,
            wo_h + (long)i * 16384, wo_l + (long)i * 16384,
            wo_b + i * 128, h, nullptr, nullptr, h, nullptr, nullptr, M, 128, 128);
        ln_k<<<lnGrid, 256>>>(h, ln2_s + i * 128, ln2_b + i * 128, lnhi, lnlo, M);
        tgemm<4><<<dim3(4, MTILES), 256, SMEMSZ>>>(lnhi, lnlo,
            wf1_h + (long)i * 512 * 128, wf1_l + (long)i * 512 * 128,
            ff_b1 + i * 512, nullptr, nullptr, nullptr, nullptr, ffhi, fflo, M, 512, 128);
        bool last = (i == NLAYER - 1);
        tgemm<3><<<dim3(1, MTILES), 256, SMEMSZ>>>(ffhi, fflo,
            wf2_h + (long)i * 128 * 512, wf2_l + (long)i * 128 * 512,
            ff_b2 + i * 128, h, nullptr, nullptr, h,
            last ? hhi : nullptr, last ? hlo : nullptr, M, 128, 512);
    }

    tgemm<5><<<dim3(1, MTILES), 256, SMEMSZ>>>(hhi, hlo, wp1_h, wp1_l, pre_b1, nullptr,
                                               pre_b2, pre_w2, out, nullptr, nullptr, M, 128, 128);
}

// round 4
// speedup vs baseline: 1.3655x; 1.0831x over previous
#include <cuda_runtime.h>
#include <cuda_bf16.h>
#include <cstdint>
#include <math.h>

#define BATCH 16
#define S1 61
#define SEQ 3721
#define DMODEL 128
#define HEADS 8
#define DH 16
#define NLAYER 4
#define FFDIM 512
#define PCH 49
#define MROWS (BATCH * SEQ) // 59536
#define MTILES ((MROWS + 127) / 128) // 466

// ---------------------------------------------------------------- scratch
__device__ __nv_bfloat16 g_phi[MROWS * 64],  g_plo[MROWS * 64];
__device__ float         g_h[MROWS * 128];
__device__ __nv_bfloat16 g_lnhi[MROWS * 128], g_lnlo[MROWS * 128];
__device__ float         g_qkv[(size_t)MROWS * 384];
__device__ __nv_bfloat16 g_atthi[MROWS * 128], g_attlo[MROWS * 128];
__device__ __nv_bfloat16 g_ffhi[(size_t)MROWS * 512], g_fflo[(size_t)MROWS * 512];
__device__ __nv_bfloat16 g_hhi[MROWS * 128], g_hlo[MROWS * 128];
__device__ __nv_bfloat16 g_wlt_h[128 * 64],  g_wlt_l[128 * 64];
__device__ __nv_bfloat16 g_wqkv_h[NLAYER * 384 * 128], g_wqkv_l[NLAYER * 384 * 128];
__device__ __nv_bfloat16 g_wo_h[NLAYER * 128 * 128],   g_wo_l[NLAYER * 128 * 128];
__device__ __nv_bfloat16 g_wf1_h[NLAYER * 512 * 128],  g_wf1_l[NLAYER * 512 * 128];
__device__ __nv_bfloat16 g_wf2_h[NLAYER * 128 * 512],  g_wf2_l[NLAYER * 128 * 512];
__device__ __nv_bfloat16 g_wp1_h[128 * 128],  g_wp1_l[128 * 128];

// ---------------------------------------------------------------- helpers
__device__ __forceinline__ uint32_t smem_u32(const void* p) {
    uint32_t a;
    asm("{ .reg .u64 t; cvta.to.shared.u64 t, %1; cvt.u32.u64 %0, t; }" : "=r"(a) : "l"(p));
    return a;
}
__device__ __forceinline__ void ldsm4(uint32_t* r, uint32_t addr) {
    asm volatile("ldmatrix.sync.aligned.m8n8.x4.shared.b16 {%0,%1,%2,%3}, [%4];"
                 : "=r"(r[0]), "=r"(r[1]), "=r"(r[2]), "=r"(r[3]) : "r"(addr));
}
__device__ __forceinline__ void mma16816(float* c, const uint32_t* a, uint32_t b0, uint32_t b1) {
    asm volatile("mma.sync.aligned.m16n8k16.row.col.f32.bf16.bf16.f32 "
                 "{%0,%1,%2,%3}, {%4,%5,%6,%7}, {%8,%9}, {%0,%1,%2,%3};"
                 : "+f"(c[0]), "+f"(c[1]), "+f"(c[2]), "+f"(c[3])
                 : "r"(a[0]), "r"(a[1]), "r"(a[2]), "r"(a[3]), "r"(b0), "r"(b1));
}
__device__ __forceinline__ void cpasync16(uint32_t saddr, const void* g, uint32_t ssz) {
    asm volatile("cp.async.cg.shared.global [%0], [%1], 16, %2;"
                 :: "r"(saddr), "l"(g), "r"(ssz));
}
#define CP_COMMIT() asm volatile("cp.async.commit_group;" ::: "memory")
#define CP_WAIT(n)  asm volatile("cp.async.wait_group %0;" :: "n"(n) : "memory")

// ------------------------------------------- batched weight transpose + split
// W[l][K,N] fp32 -> Wt[l][N,Kp] bf16 hi/lo (zero pad K..Kp)
__global__ void wprep_k(const float* __restrict__ W, __nv_bfloat16* __restrict__ hi,
                        __nv_bfloat16* __restrict__ lo, int K, int N, int Kp,
                        long sstride, long dstride, int L) {
    long t = (long)blockIdx.x * blockDim.x + threadIdx.x;
    if (t >= (long)L * N * Kp) return;
    int l = (int)(t / (N * Kp));
    int r = (int)(t % (N * Kp));
    int n = r / Kp, kk = r % Kp;
    float v = (kk < K) ? W[l * sstride + (long)kk * N + n] : 0.f;
    __nv_bfloat16 h = __float2bfloat16(v);
    hi[l * dstride + r] = h;
    lo[l * dstride + r] = __float2bfloat16(v - __bfloat162float(h));
}

// ---------------- conv 7x7 'same' + relu -> bf16 hi/lo [M,64] ----------------
__global__ void conv_k(const float* __restrict__ x, const float* __restrict__ cw,
                       const float* __restrict__ cb, __nv_bfloat16* __restrict__ phi,
                       __nv_bfloat16* __restrict__ plo) {
    int t = blockIdx.x * blockDim.x + threadIdx.x;
    if (t >= MROWS * 64) return;
    int o = t & 63;
    float sum = 0.f;
    if (o < PCH) {
        int s = (t >> 6) % SEQ;
        int b = (t >> 6) / SEQ;
        int y = s / S1, xx = s % S1;
        const float* xb = x + (long)b * SEQ;
        const float* wo = cw + o * 49;
        sum = cb[o];
#pragma unroll
        for (int dy = 0; dy < 7; dy++) {
            int iy = y + dy - 3;
            if (iy < 0 || iy >= S1) continue;
#pragma unroll
            for (int dx = 0; dx < 7; dx++) {
                int ix = xx + dx - 3;
                if (ix < 0 || ix >= S1) continue;
                sum += xb[iy * S1 + ix] * wo[dy * 7 + dx];
            }
        }
        sum = fmaxf(sum, 0.f);
    }
    __nv_bfloat16 h = __float2bfloat16(sum);
    phi[t] = h;
    plo[t] = __float2bfloat16(sum - __bfloat162float(h));
}

// ---------------- layernorm: warp per row -> bf16 hi/lo ----------------------
__global__ void ln_k(const float* __restrict__ x, const float* __restrict__ sc,
                     const float* __restrict__ bi, __nv_bfloat16* __restrict__ ohi,
                     __nv_bfloat16* __restrict__ olo, int M) {
    int warp = (blockIdx.x * blockDim.x + threadIdx.x) >> 5;
    int lane = threadIdx.x & 31;
    if (warp >= M) return;
    float4 v = ((const float4*)(x + (long)warp * DMODEL))[lane];
    float sum = v.x + v.y + v.z + v.w;
#pragma unroll
    for (int off = 16; off; off >>= 1) sum += __shfl_xor_sync(~0u, sum, off);
    float mean = sum * (1.f / 128.f);
    float dx = v.x - mean, dy = v.y - mean, dz = v.z - mean, dw = v.w - mean;
    float vs = dx * dx + dy * dy + dz * dz + dw * dw;
#pragma unroll
    for (int off = 16; off; off >>= 1) vs += __shfl_xor_sync(~0u, vs, off);
    float inv = rsqrtf(vs * (1.f / 128.f) + 1e-5f);
    float4 s4 = ((const float4*)sc)[lane];
    float4 b4 = ((const float4*)bi)[lane];
    float o[4] = {dx * inv * s4.x + b4.x, dy * inv * s4.y + b4.y,
                  dz * inv * s4.z + b4.z, dw * inv * s4.w + b4.w};
    __nv_bfloat16 hv[4], lv[4];
#pragma unroll
    for (int i = 0; i < 4; i++) {
        hv[i] = __float2bfloat16(o[i]);
        lv[i] = __float2bfloat16(o[i] - __bfloat162float(hv[i]));
    }
    *(uint2*)(ohi + (long)warp * 128 + lane * 4) = *(uint2*)hv;
    *(uint2*)(olo + (long)warp * 128 + lane * 4) = *(uint2*)lv;
}

// ---------------- pipelined mma.sync GEMM, 3-MMA fp32 emulation --------------
// C[M,N] = A[M,K] @ Bt[N,K]^T; CTA tile 128x128, BK=64, 3-stage cp.async.
// EPI: 0 fp32 C; 2 +bias+pos; 3 +bias+res (fp32, optional hi/lo);
//      4 gelu(+bias)->hi/lo; 5 head: C[row]=sum relu(acc+bias)*w2 + pos[0]
#define TILE_B 16384u
#define STAGE_B 65536u
#define NSTAGE 3
#define SMEMSZ (NSTAGE * 65536)

template <int EPI>
__global__ void __launch_bounds__(256, 1)
tgemm(const __nv_bfloat16* __restrict__ Ah, const __nv_bfloat16* __restrict__ Al,
      const __nv_bfloat16* __restrict__ Bh, const __nv_bfloat16* __restrict__ Bl,
      const float* __restrict__ bias, const float* __restrict__ res,
      const float* __restrict__ pos, const float* __restrict__ w2,
      float* __restrict__ C, __nv_bfloat16* __restrict__ Chi,
      __nv_bfloat16* __restrict__ Clo, int M, int N, int K) {
    extern __shared__ char sm[];
    __shared__ float red[2][128];
    uint32_t sb = smem_u32(sm);
    int tid = threadIdx.x;
    int w = tid >> 5, lane = tid & 31;
    int wm = w & 3, wn = w >> 2;
    int m0 = blockIdx.y * 128, n0 = blockIdx.x * 128;
    int nk = K >> 6;

    float acc[2][8][4];
#pragma unroll
    for (int i = 0; i < 2; i++)
#pragma unroll
        for (int j = 0; j < 8; j++)
#pragma unroll
            for (int q = 0; q < 4; q++) acc[i][j][q] = 0.f;

    int rA[2], rB[4];
#pragma unroll
    for (int mi = 0; mi < 2; mi++) rA[mi] = wm * 32 + mi * 16 + (lane & 15);
#pragma unroll
    for (int ng = 0; ng < 4; ng++)
        rB[ng] = wn * 64 + ng * 16 + ((lane >> 4) << 3) + (lane & 7);
    int cA = lane >> 4;
    int cB = (lane >> 3) & 1;

    // per-thread load mapping (16 x 16B per stage)
    auto load_stage = [&](int c, int buf) {
#pragma unroll
        for (int it = 0; it < 16; it++) {
            int slot = it * 256 + tid;
            int t = it >> 2;
            int row = (slot >> 3) & 127;
            int chunk = slot & 7;
            const __nv_bfloat16* src = (t == 0) ? Ah : (t == 1) ? Al : (t == 2) ? Bh : Bl;
            long grow = (t < 2) ? (long)(m0 + row) : (long)(n0 + row);
            bool ok = (t < 2) ? (m0 + row < M) : true;
            if (!ok) grow = 0;
            const void* g = (const void*)(src + grow * K + ((long)c << 6) + chunk * 8);
            uint32_t saddr = sb + buf * STAGE_B + (uint32_t)t * TILE_B + row * 128 +
                             ((chunk ^ (row & 7)) << 4);
            cpasync16(saddr, g, ok ? 16u : 0u);
        }
        CP_COMMIT();
    };

    // prologue: prefetch up to NSTAGE-1 chunks
#pragma unroll
    for (int p = 0; p < NSTAGE - 1; p++)
        if (p < nk) load_stage(p, p);

    for (int c = 0; c < nk; c++) {
        int nxt = c + NSTAGE - 1;
        if (nxt < nk) load_stage(nxt, nxt % NSTAGE);
        int allow = (nxt < nk ? nxt : nk - 1) - c;  // groups allowed pending
        if (allow >= 2) CP_WAIT(2);
        else if (allow == 1) CP_WAIT(1);
        else CP_WAIT(0);
        __syncthreads();

        uint32_t st = sb + (c % NSTAGE) * STAGE_B;
#pragma unroll
        for (int ks = 0; ks < 4; ks++) {
            int kc = ks * 2;
            uint32_t Ahf[2][4], Alf[2][4], Bhf[4][4], Blf[4][4];
#pragma unroll
            for (int mi = 0; mi < 2; mi++) {
                int row = rA[mi];
                uint32_t off = row * 128 + (((kc + cA) ^ (row & 7)) << 4);
                ldsm4(Ahf[mi], st + off);
                ldsm4(Alf[mi], st + TILE_B + off);
            }
#pragma unroll
            for (int ng = 0; ng < 4; ng++) {
                int row = rB[ng];
                uint32_t off = row * 128 + (((kc + cB) ^ (row & 7)) << 4);
                ldsm4(Bhf[ng], st + 2 * TILE_B + off);
                ldsm4(Blf[ng], st + 3 * TILE_B + off);
            }
            // hi*hi
#pragma unroll
            for (int ng = 0; ng < 4; ng++)
#pragma unroll
                for (int mi = 0; mi < 2; mi++) {
                    mma16816(acc[mi][ng * 2],     Ahf[mi], Bhf[ng][0], Bhf[ng][1]);
                    mma16816(acc[mi][ng * 2 + 1], Ahf[mi], Bhf[ng][2], Bhf[ng][3]);
                }
            // lo*hi
#pragma unroll
            for (int ng = 0; ng < 4; ng++)
#pragma unroll
                for (int mi = 0; mi < 2; mi++) {
                    mma16816(acc[mi][ng * 2],     Alf[mi], Bhf[ng][0], Bhf[ng][1]);
                    mma16816(acc[mi][ng * 2 + 1], Alf[mi], Bhf[ng][2], Bhf[ng][3]);
                }
            // hi*lo
#pragma unroll
            for (int ng = 0; ng < 4; ng++)
#pragma unroll
                for (int mi = 0; mi < 2; mi++) {
                    mma16816(acc[mi][ng * 2],     Ahf[mi], Blf[ng][0], Blf[ng][1]);
                    mma16816(acc[mi][ng * 2 + 1], Ahf[mi], Blf[ng][2], Blf[ng][3]);
                }
        }
        __syncthreads();
    }

    // ---------------- epilogue ----------------
    int tg = lane >> 2;
    int tc = (lane & 3) * 2;
    if (EPI == 5) {
        float p[2][2] = {};
#pragma unroll
        for (int mi = 0; mi < 2; mi++)
#pragma unroll
            for (int ni = 0; ni < 8; ni++) {
                int col = wn * 64 + ni * 8 + tc;
                float b0 = bias[col], b1 = bias[col + 1];
                float w20 = w2[col], w21 = w2[col + 1];
                p[mi][0] += fmaxf(acc[mi][ni][0] + b0, 0.f) * w20 +
                            fmaxf(acc[mi][ni][1] + b1, 0.f) * w21;
                p[mi][1] += fmaxf(acc[mi][ni][2] + b0, 0.f) * w20 +
                            fmaxf(acc[mi][ni][3] + b1, 0.f) * w21;
            }
#pragma unroll
        for (int mi = 0; mi < 2; mi++)
#pragma unroll
            for (int hf = 0; hf < 2; hf++) {
                float v = p[mi][hf];
                v += __shfl_xor_sync(~0u, v, 1);
                v += __shfl_xor_sync(~0u, v, 2);
                if ((lane & 3) == 0) red[wn][wm * 32 + mi * 16 + hf * 8 + tg] = v;
            }
        __syncthreads();
        if (tid < 128) {
            int row = m0 + tid;
            if (row < M) C[row] = red[0][tid] + red[1][tid] + pos[0];
        }
        return;
    }

#pragma unroll
    for (int mi = 0; mi < 2; mi++) {
#pragma unroll
        for (int hf = 0; hf < 2; hf++) {
            int row = m0 + wm * 32 + mi * 16 + hf * 8 + tg;
            if (row >= M) continue;
#pragma unroll
            for (int ni = 0; ni < 8; ni++) {
                int col = n0 + wn * 64 + ni * 8 + tc;
                float v0 = acc[mi][ni][hf * 2 + 0];
                float v1 = acc[mi][ni][hf * 2 + 1];
                if (EPI == 0) {
                    *(float2*)&C[(long)row * N + col] = make_float2(v0, v1);
                } else if (EPI == 2) {
                    long pr = (long)(row % SEQ) * 128 + col;
                    v0 += bias[col] + pos[pr];
                    v1 += bias[col + 1] + pos[pr + 1];
                    *(float2*)&C[(long)row * N + col] = make_float2(v0, v1);
                } else if (EPI == 3) {
                    v0 += bias[col] + res[(long)row * N + col];
                    v1 += bias[col + 1] + res[(long)row * N + col + 1];
                    *(float2*)&C[(long)row * N + col] = make_float2(v0, v1);
                    if (Chi) {
                        __nv_bfloat16 h0 = __float2bfloat16(v0), h1 = __float2bfloat16(v1);
                        __nv_bfloat16 hl[2] = {h0, h1};
                        __nv_bfloat16 ll[2] = {__float2bfloat16(v0 - __bfloat162float(h0)),
                                               __float2bfloat16(v1 - __bfloat162float(h1))};
                        *(uint32_t*)&Chi[(long)row * N + col] = *(uint32_t*)hl;
                        *(uint32_t*)&Clo[(long)row * N + col] = *(uint32_t*)ll;
                    }
                } else { // EPI 4: gelu -> hi/lo
                    v0 += bias[col];
                    v1 += bias[col + 1];
                    v0 = 0.5f * v0 * (1.f + erff(v0 * 0.70710678118654752f));
                    v1 = 0.5f * v1 * (1.f + erff(v1 * 0.70710678118654752f));
                    __nv_bfloat16 h0 = __float2bfloat16(v0), h1 = __float2bfloat16(v1);
                    __nv_bfloat16 hl[2] = {h0, h1};
                    __nv_bfloat16 ll[2] = {__float2bfloat16(v0 - __bfloat162float(h0)),
                                           __float2bfloat16(v1 - __bfloat162float(h1))};
                    *(uint32_t*)&Chi[(long)row * N + col] = *(uint32_t*)hl;
                    *(uint32_t*)&Clo[(long)row * N + col] = *(uint32_t*)ll;
                }
            }
        }
    }
}

// ---------------- local windowed attention -----------------------------------
__global__ void attn_k(const float* __restrict__ qkv, __nv_bfloat16* __restrict__ ohi,
                       __nv_bfloat16* __restrict__ olo) {
    __shared__ float qs[S1][17];
    __shared__ float ks[3 * S1][17];
    __shared__ float vs[3 * S1][17];
    __shared__ float ps[8][192];
    int w = blockIdx.x;
    int bh = blockIdx.y;
    int b = bh >> 3, h = bh & 7;
    int tid = threadIdx.x;
    int jstart = (w > 0) ? 0 : S1;
    int jend = (w < S1 - 1) ? 3 * S1 : 2 * S1;
    long rb = (long)b * SEQ;

    for (int idx = tid; idx < S1 * DH; idx += 256) {
        int i = idx >> 4, d = idx & 15;
        qs[i][d] = qkv[(rb + w * S1 + i) * 384 + h * 16 + d] * 0.25f;
    }
    int cnt = jend - jstart;
    for (int idx = tid; idx < cnt * DH; idx += 256) {
        int j = jstart + (idx >> 4), d = idx & 15;
        long r = rb + (long)(w - 1) * S1 + j;
        ks[j][d] = qkv[r * 384 + 128 + h * 16 + d];
        vs[j][d] = qkv[r * 384 + 256 + h * 16 + d];
    }
    __syncthreads();

    int warp = tid >> 5, lane = tid & 31;
    for (int i = warp; i < S1; i += 8) {
        float ql[DH];
#pragma unroll
        for (int d = 0; d < DH; d++) ql[d] = qs[i][d];
        float sc[6];
        float mx = -1e30f;
        int c = 0;
        for (int j = jstart + lane; j < jend; j += 32) {
            float s = 0.f;
#pragma unroll
            for (int d = 0; d < DH; d++) s += ql[d] * ks[j][d];
            sc[c++] = s;
            mx = fmaxf(mx, s);
        }
#pragma unroll
        for (int off = 16; off; off >>= 1) mx = fmaxf(mx, __shfl_xor_sync(~0u, mx, off));
        float se = 0.f;
        c = 0;
        for (int j = jstart + lane; j < jend; j += 32) {
            float p = __expf(sc[c] - mx);
            sc[c++] = p;
            se += p;
        }
#pragma unroll
        for (int off = 16; off; off >>= 1) se += __shfl_xor_sync(~0u, se, off);
        float inv = 1.f / se;
        c = 0;
        for (int j = jstart + lane; j < jend; j += 32) ps[warp][j - jstart] = sc[c++] * inv;
        __syncwarp();
        int d = lane & 15, half = lane >> 4;
        float accv = 0.f;
        for (int jj = half; jj < cnt; jj += 2) accv += ps[warp][jj] * vs[jstart + jj][d];
        accv += __shfl_xor_sync(~0u, accv, 16);
        if (lane < 16) {
            long orow = (rb + w * S1 + i) * 128 + h * 16 + d;
            __nv_bfloat16 hv = __float2bfloat16(accv);
            ohi[orow] = hv;
            olo[orow] = __float2bfloat16(accv - __bfloat162float(hv));
        }
        __syncwarp();
    }
}

// ---------------- launch ------------------------------------------------------
extern "C" void kernel_launch(void* const* d_in, const int* in_sizes, int n_in,
                              void* d_out, int out_size) {
    const float* x      = (const float*)d_in[0];
    const float* conv_w = (const float*)d_in[1];
    const float* conv_b = (const float*)d_in[2];
    const float* lt_w   = (const float*)d_in[3];
    const float* lt_b   = (const float*)d_in[4];
    const float* pos    = (const float*)d_in[5];
    const float* ln1_s  = (const float*)d_in[6];
    const float* ln1_b  = (const float*)d_in[7];
    const float* wq     = (const float*)d_in[8];
    const float* wk     = (const float*)d_in[9];
    const float* wv     = (const float*)d_in[10];
    const float* wo     = (const float*)d_in[11];
    const float* wo_b   = (const float*)d_in[12];
    const float* ln2_s  = (const float*)d_in[13];
    const float* ln2_b  = (const float*)d_in[14];
    const float* ff_w1  = (const float*)d_in[15];
    const float* ff_b1  = (const float*)d_in[16];
    const float* ff_w2  = (const float*)d_in[17];
    const float* ff_b2  = (const float*)d_in[18];
    const float* pre_w1 = (const float*)d_in[19];
    const float* pre_b1 = (const float*)d_in[20];
    const float* pre_w2 = (const float*)d_in[21];
    const float* pre_b2 = (const float*)d_in[22];
    float* out = (float*)d_out;

    static bool attr_done = false;
    if (!attr_done) {
        cudaFuncSetAttribute(tgemm<0>, cudaFuncAttributeMaxDynamicSharedMemorySize, SMEMSZ);
        cudaFuncSetAttribute(tgemm<2>, cudaFuncAttributeMaxDynamicSharedMemorySize, SMEMSZ);
        cudaFuncSetAttribute(tgemm<3>, cudaFuncAttributeMaxDynamicSharedMemorySize, SMEMSZ);
        cudaFuncSetAttribute(tgemm<4>, cudaFuncAttributeMaxDynamicSharedMemorySize, SMEMSZ);
        cudaFuncSetAttribute(tgemm<5>, cudaFuncAttributeMaxDynamicSharedMemorySize, SMEMSZ);
        attr_done = true;
    }

    __nv_bfloat16 *phi, *plo, *lnhi, *lnlo, *atthi, *attlo, *ffhi, *fflo, *hhi, *hlo;
    __nv_bfloat16 *wlt_h, *wlt_l, *wqkv_h, *wqkv_l, *wo_h, *wo_l, *wf1_h, *wf1_l, *wf2_h, *wf2_l, *wp1_h, *wp1_l;
    float *h, *qkv;
    cudaGetSymbolAddress((void**)&phi, g_phi);     cudaGetSymbolAddress((void**)&plo, g_plo);
    cudaGetSymbolAddress((void**)&h, g_h);         cudaGetSymbolAddress((void**)&qkv, g_qkv);
    cudaGetSymbolAddress((void**)&lnhi, g_lnhi);   cudaGetSymbolAddress((void**)&lnlo, g_lnlo);
    cudaGetSymbolAddress((void**)&atthi, g_atthi); cudaGetSymbolAddress((void**)&attlo, g_attlo);
    cudaGetSymbolAddress((void**)&ffhi, g_ffhi);   cudaGetSymbolAddress((void**)&fflo, g_fflo);
    cudaGetSymbolAddress((void**)&hhi, g_hhi);     cudaGetSymbolAddress((void**)&hlo, g_hlo);
    cudaGetSymbolAddress((void**)&wlt_h, g_wlt_h); cudaGetSymbolAddress((void**)&wlt_l, g_wlt_l);
    cudaGetSymbolAddress((void**)&wqkv_h, g_wqkv_h); cudaGetSymbolAddress((void**)&wqkv_l, g_wqkv_l);
    cudaGetSymbolAddress((void**)&wo_h, g_wo_h);   cudaGetSymbolAddress((void**)&wo_l, g_wo_l);
    cudaGetSymbolAddress((void**)&wf1_h, g_wf1_h); cudaGetSymbolAddress((void**)&wf1_l, g_wf1_l);
    cudaGetSymbolAddress((void**)&wf2_h, g_wf2_h); cudaGetSymbolAddress((void**)&wf2_l, g_wf2_l);
    cudaGetSymbolAddress((void**)&wp1_h, g_wp1_h); cudaGetSymbolAddress((void**)&wp1_l, g_wp1_l);

    // ---- batched weight prep ----
    auto wp = [&](const float* W, __nv_bfloat16* hi, __nv_bfloat16* lo, int K, int N, int Kp,
                  long ss, long ds, int L) {
        long n = (long)L * N * Kp;
        wprep_k<<<(int)((n + 255) / 256), 256>>>(W, hi, lo, K, N, Kp, ss, ds, L);
    };
    wp(lt_w, wlt_h, wlt_l, 49, 128, 64, 0, 0, 1);
    wp(pre_w1, wp1_h, wp1_l, 128, 128, 128, 0, 0, 1);
    wp(wq, wqkv_h, wqkv_l, 128, 128, 128, 16384, 384 * 128, NLAYER);
    wp(wk, wqkv_h + 128 * 128, wqkv_l + 128 * 128, 128, 128, 128, 16384, 384 * 128, NLAYER);
    wp(wv, wqkv_h + 256 * 128, wqkv_l + 256 * 128, 128, 128, 128, 16384, 384 * 128, NLAYER);
    wp(wo, wo_h, wo_l, 128, 128, 128, 16384, 16384, NLAYER);
    wp(ff_w1, wf1_h, wf1_l, 128, 512, 128, 128 * 512, 512 * 128, NLAYER);
    wp(ff_w2, wf2_h, wf2_l, 512, 128, 512, 512 * 128, 128 * 512, NLAYER);

    const int M = MROWS;
    int lnGrid = (M + 7) / 8;

    conv_k<<<(MROWS * 64 + 255) / 256, 256>>>(x, conv_w, conv_b, phi, plo);
    tgemm<2><<<dim3(1, MTILES), 256, SMEMSZ>>>(phi, plo, wlt_h, wlt_l, lt_b, nullptr, pos,
                                               nullptr, h, nullptr, nullptr, M, 128, 64);

    for (int i = 0; i < NLAYER; i++) {
        ln_k<<<lnGrid, 256>>>(h, ln1_s + i * 128, ln1_b + i * 128, lnhi, lnlo, M);
        tgemm<0><<<dim3(3, MTILES), 256, SMEMSZ>>>(lnhi, lnlo,
            wqkv_h + (long)i * 384 * 128, wqkv_l + (long)i * 384 * 128,
            nullptr, nullptr, nullptr, nullptr, qkv, nullptr, nullptr, M, 384, 128);
        attn_k<<<dim3(S1, BATCH * HEADS), 256>>>(qkv, atthi, attlo);
        tgemm<3><<<dim3(1, MTILES), 256, SMEMSZ>>>(atthi, attlo,
            wo_h + (long)i * 16384, wo_l + (long)i * 16384,
            wo_b + i * 128, h, nullptr, nullptr, h, nullptr, nullptr, M, 128, 128);
        ln_k<<<lnGrid, 256>>>(h, ln2_s + i * 128, ln2_b + i * 128, lnhi, lnlo, M);
        tgemm<4><<<dim3(4, MTILES), 256, SMEMSZ>>>(lnhi, lnlo,
            wf1_h + (long)i * 512 * 128, wf1_l + (long)i * 512 * 128,
            ff_b1 + i * 512, nullptr, nullptr, nullptr, nullptr, ffhi, fflo, M, 512, 128);
        bool last = (i == NLAYER - 1);
        tgemm<3><<<dim3(1, MTILES), 256, SMEMSZ>>>(ffhi, fflo,
            wf2_h + (long)i * 128 * 512, wf2_l + (long)i * 128 * 512,
            ff_b2 + i * 128, h, nullptr, nullptr, h,
            last ? hhi : nullptr, last ? hlo : nullptr, M, 128, 512);
    }

    tgemm<5><<<dim3(1, MTILES), 256, SMEMSZ>>>(hhi, hlo, wp1_h, wp1_l, pre_b1, nullptr,
                                               pre_b2, pre_w2, out, nullptr, nullptr, M, 128, 128);
}

// round 5
// speedup vs baseline: 1.3765x; 1.0080x over previous
#include <cuda_runtime.h>
#include <cuda_bf16.h>
#include <cstdint>
#include <math.h>

#define BATCH 16
#define S1 61
#define SEQ 3721
#define DMODEL 128
#define HEADS 8
#define DH 16
#define NLAYER 4
#define FFDIM 512
#define PCH 49
#define MROWS (BATCH * SEQ) // 59536
#define MTILES ((MROWS + 127) / 128) // 466

// ---------------------------------------------------------------- scratch
__device__ __nv_bfloat16 g_phi[MROWS * 64],  g_plo[MROWS * 64];
__device__ float         g_h[MROWS * 128];
__device__ __nv_bfloat16 g_lnhi[MROWS * 128], g_lnlo[MROWS * 128];
__device__ float         g_qkv[(size_t)MROWS * 384];
__device__ __nv_bfloat16 g_atthi[MROWS * 128], g_attlo[MROWS * 128];
__device__ __nv_bfloat16 g_ffhi[(size_t)MROWS * 512], g_fflo[(size_t)MROWS * 512];
__device__ __nv_bfloat16 g_hhi[MROWS * 128], g_hlo[MROWS * 128];
__device__ __nv_bfloat16 g_wlt_h[128 * 64],  g_wlt_l[128 * 64];
__device__ __nv_bfloat16 g_wqkv_h[NLAYER * 384 * 128], g_wqkv_l[NLAYER * 384 * 128];
__device__ __nv_bfloat16 g_wo_h[NLAYER * 128 * 128],   g_wo_l[NLAYER * 128 * 128];
__device__ __nv_bfloat16 g_wf1_h[NLAYER * 512 * 128],  g_wf1_l[NLAYER * 512 * 128];
__device__ __nv_bfloat16 g_wf2_h[NLAYER * 128 * 512],  g_wf2_l[NLAYER * 128 * 512];
__device__ __nv_bfloat16 g_wp1_h[128 * 128],  g_wp1_l[128 * 128];

// ---------------------------------------------------------------- helpers
__device__ __forceinline__ uint32_t smem_u32(const void* p) {
    uint32_t a;
    asm("{ .reg .u64 t; cvta.to.shared.u64 t, %1; cvt.u32.u64 %0, t; }" : "=r"(a) : "l"(p));
    return a;
}
__device__ __forceinline__ void ldsm4(uint32_t* r, uint32_t addr) {
    asm volatile("ldmatrix.sync.aligned.m8n8.x4.shared.b16 {%0,%1,%2,%3}, [%4];"
                 : "=r"(r[0]), "=r"(r[1]), "=r"(r[2]), "=r"(r[3]) : "r"(addr));
}
__device__ __forceinline__ void mma16816(float* c, const uint32_t* a, uint32_t b0, uint32_t b1) {
    asm volatile("mma.sync.aligned.m16n8k16.row.col.f32.bf16.bf16.f32 "
                 "{%0,%1,%2,%3}, {%4,%5,%6,%7}, {%8,%9}, {%0,%1,%2,%3};"
                 : "+f"(c[0]), "+f"(c[1]), "+f"(c[2]), "+f"(c[3])
                 : "r"(a[0]), "r"(a[1]), "r"(a[2]), "r"(a[3]), "r"(b0), "r"(b1));
}
__device__ __forceinline__ void cpasync16(uint32_t saddr, const void* g, uint32_t ssz) {
    asm volatile("cp.async.cg.shared.global [%0], [%1], 16, %2;"
                 :: "r"(saddr), "l"(g), "r"(ssz));
}
#define CP_COMMIT() asm volatile("cp.async.commit_group;" ::: "memory")
#define CP_WAIT(n)  asm volatile("cp.async.wait_group %0;" :: "n"(n) : "memory")

// ------------------------------------------- weight prep kernels
__global__ void wprep_k(const float* __restrict__ W, __nv_bfloat16* __restrict__ hi,
                        __nv_bfloat16* __restrict__ lo, int K, int N, int Kp,
                        long sstride, long dstride, int L) {
    long t = (long)blockIdx.x * blockDim.x + threadIdx.x;
    if (t >= (long)L * N * Kp) return;
    int l = (int)(t / (N * Kp));
    int r = (int)(t % (N * Kp));
    int n = r / Kp, kk = r % Kp;
    float v = (kk < K) ? W[l * sstride + (long)kk * N + n] : 0.f;
    __nv_bfloat16 h = __float2bfloat16(v);
    hi[l * dstride + r] = h;
    lo[l * dstride + r] = __float2bfloat16(v - __bfloat162float(h));
}

// fused q/k/v transpose+split into [L][384][128]
__global__ void qkvprep_k(const float* __restrict__ wq, const float* __restrict__ wk,
                          const float* __restrict__ wv, __nv_bfloat16* __restrict__ hi,
                          __nv_bfloat16* __restrict__ lo) {
    long t = (long)blockIdx.x * blockDim.x + threadIdx.x;
    if (t >= (long)NLAYER * 384 * 128) return;
    int l = (int)(t / (384 * 128));
    int r = (int)(t % (384 * 128));
    int n = r / 128, kk = r % 128;
    int s = n >> 7, nn = n & 127;
    const float* W = (s == 0 ? wq : s == 1 ? wk : wv) + (long)l * 16384;
    float v = W[kk * 128 + nn];
    __nv_bfloat16 h = __float2bfloat16(v);
    hi[(long)l * 49152 + r] = h;
    lo[(long)l * 49152 + r] = __float2bfloat16(v - __bfloat162float(h));
}

// ---------------- conv 7x7 'same' + relu -> bf16 hi/lo [M,64] ----------------
__global__ void conv_k(const float* __restrict__ x, const float* __restrict__ cw,
                       const float* __restrict__ cb, __nv_bfloat16* __restrict__ phi,
                       __nv_bfloat16* __restrict__ plo) {
    int t = blockIdx.x * blockDim.x + threadIdx.x;
    if (t >= MROWS * 64) return;
    int o = t & 63;
    float sum = 0.f;
    if (o < PCH) {
        int s = (t >> 6) % SEQ;
        int b = (t >> 6) / SEQ;
        int y = s / S1, xx = s % S1;
        const float* xb = x + (long)b * SEQ;
        const float* wo = cw + o * 49;
        sum = cb[o];
#pragma unroll
        for (int dy = 0; dy < 7; dy++) {
            int iy = y + dy - 3;
            if (iy < 0 || iy >= S1) continue;
#pragma unroll
            for (int dx = 0; dx < 7; dx++) {
                int ix = xx + dx - 3;
                if (ix < 0 || ix >= S1) continue;
                sum += xb[iy * S1 + ix] * wo[dy * 7 + dx];
            }
        }
        sum = fmaxf(sum, 0.f);
    }
    __nv_bfloat16 h = __float2bfloat16(sum);
    phi[t] = h;
    plo[t] = __float2bfloat16(sum - __bfloat162float(h));
}

// ---------------- layernorm: warp per row -> bf16 hi/lo ----------------------
__global__ void ln_k(const float* __restrict__ x, const float* __restrict__ sc,
                     const float* __restrict__ bi, __nv_bfloat16* __restrict__ ohi,
                     __nv_bfloat16* __restrict__ olo, int M) {
    int warp = (blockIdx.x * blockDim.x + threadIdx.x) >> 5;
    int lane = threadIdx.x & 31;
    if (warp >= M) return;
    float4 v = ((const float4*)(x + (long)warp * DMODEL))[lane];
    float sum = v.x + v.y + v.z + v.w;
#pragma unroll
    for (int off = 16; off; off >>= 1) sum += __shfl_xor_sync(~0u, sum, off);
    float mean = sum * (1.f / 128.f);
    float dx = v.x - mean, dy = v.y - mean, dz = v.z - mean, dw = v.w - mean;
    float vs = dx * dx + dy * dy + dz * dz + dw * dw;
#pragma unroll
    for (int off = 16; off; off >>= 1) vs += __shfl_xor_sync(~0u, vs, off);
    float inv = rsqrtf(vs * (1.f / 128.f) + 1e-5f);
    float4 s4 = ((const float4*)sc)[lane];
    float4 b4 = ((const float4*)bi)[lane];
    float o[4] = {dx * inv * s4.x + b4.x, dy * inv * s4.y + b4.y,
                  dz * inv * s4.z + b4.z, dw * inv * s4.w + b4.w};
    __nv_bfloat16 hv[4], lv[4];
#pragma unroll
    for (int i = 0; i < 4; i++) {
        hv[i] = __float2bfloat16(o[i]);
        lv[i] = __float2bfloat16(o[i] - __bfloat162float(hv[i]));
    }
    *(uint2*)(ohi + (long)warp * 128 + lane * 4) = *(uint2*)hv;
    *(uint2*)(olo + (long)warp * 128 + lane * 4) = *(uint2*)lv;
}

// =============== A-resident GEMM (K<=128), N-loop inside, frag pipeline ======
// C[M,NT*128] = A[M,K] @ Bt[NT*128,K]^T.  A (hi+lo, all K) resident in smem.
// EPI: 0 fp32; 2 +bias+pos; 3 +bias+res (fp32); 4 gelu(+bias)->hi/lo;
//      5 head row-reduce
#define SMEMA 65536u
#define SMEMB 65536u
#define SMEMSZ (SMEMA + 2 * SMEMB)

template <int EPI, int NK>
__global__ void __launch_bounds__(256, 1)
tgemmA(const __nv_bfloat16* __restrict__ Ah, const __nv_bfloat16* __restrict__ Al,
       const __nv_bfloat16* __restrict__ Bh, const __nv_bfloat16* __restrict__ Bl,
       const float* __restrict__ bias, const float* __restrict__ res,
       const float* __restrict__ pos, const float* __restrict__ w2,
       float* __restrict__ C, __nv_bfloat16* __restrict__ Chi,
       __nv_bfloat16* __restrict__ Clo, int M, int Nfull, int NT) {
    extern __shared__ char sm[];
    __shared__ float red[2][128];
    uint32_t sb = smem_u32(sm);
    const int K = NK * 64;
    int tid = threadIdx.x;
    int w = tid >> 5, lane = tid & 31;
    int wm = w & 3, wn = w >> 2;
    int m0 = blockIdx.y * 128;

    int rA[2], rB[4];
#pragma unroll
    for (int mi = 0; mi < 2; mi++) rA[mi] = wm * 32 + mi * 16 + (lane & 15);
#pragma unroll
    for (int ng = 0; ng < 4; ng++)
        rB[ng] = wn * 64 + ng * 16 + ((lane >> 4) << 3) + (lane & 7);
    int cA = lane >> 4;
    int cB = (lane >> 3) & 1;

    // ---- load A (NK*2 tiles of 16KB) once ----
#pragma unroll
    for (int t = 0; t < NK * 8; t++) {
        int slot = t * 256 + tid;
        int tile = slot >> 10;          // chunk*2 + h
        int idx = slot & 1023;
        int row = idx >> 3, c16 = idx & 7;
        int chunk = tile >> 1, hh = tile & 1;
        const __nv_bfloat16* src = hh ? Al : Ah;
        long grow = m0 + row;
        bool ok = grow < M;
        if (!ok) grow = 0;
        cpasync16(sb + (uint32_t)tile * 16384u + row * 128 + (((uint32_t)c16 ^ (row & 7)) << 4),
                  src + grow * K + chunk * 64 + c16 * 8, ok ? 16u : 0u);
    }
    CP_COMMIT();

    auto loadB = [&](int nt) {
#pragma unroll
        for (int t = 0; t < NK * 8; t++) {
            int slot = t * 256 + tid;
            int tile = slot >> 10;
            int idx = slot & 1023;
            int row = idx >> 3, c16 = idx & 7;
            int chunk = tile >> 1, hh = tile & 1;
            const __nv_bfloat16* src = hh ? Bl : Bh;
            long grow = (long)(nt * 128 + row);
            cpasync16(sb + SMEMA + (uint32_t)(nt & 1) * SMEMB + (uint32_t)tile * 16384u +
                          row * 128 + (((uint32_t)c16 ^ (row & 7)) << 4),
                      src + grow * K + chunk * 64 + c16 * 8, 16u);
        }
        CP_COMMIT();
    };
    loadB(0);

    for (int nt = 0; nt < NT; nt++) {
        if (nt + 1 < NT) { loadB(nt + 1); CP_WAIT(1); }
        else             { CP_WAIT(0); }
        __syncthreads();

        float acc[2][8][4];
#pragma unroll
        for (int i = 0; i < 2; i++)
#pragma unroll
            for (int j = 0; j < 8; j++)
#pragma unroll
                for (int q = 0; q < 4; q++) acc[i][j][q] = 0.f;

        uint32_t Bbase = sb + SMEMA + (uint32_t)(nt & 1) * SMEMB;
        uint32_t fr[2][48];

        // fragment loader: step i -> chunk=i>>2, ks=i&3
        auto ldfrag = [&](int i, uint32_t (&F)[48]) {
            int chunk = i >> 2, ks = i & 3, kc = ks * 2;
            uint32_t Ab = sb + (uint32_t)chunk * 32768u;
            uint32_t Bb = Bbase + (uint32_t)chunk * 32768u;
#pragma unroll
            for (int mi = 0; mi < 2; mi++) {
                int row = rA[mi];
                uint32_t off = row * 128 + ((((uint32_t)(kc + cA)) ^ (row & 7)) << 4);
                ldsm4(&F[mi * 4], Ab + off);
                ldsm4(&F[8 + mi * 4], Ab + 16384u + off);
            }
#pragma unroll
            for (int ng = 0; ng < 4; ng++) {
                int row = rB[ng];
                uint32_t off = row * 128 + ((((uint32_t)(kc + cB)) ^ (row & 7)) << 4);
                ldsm4(&F[16 + ng * 4], Bb + off);
                ldsm4(&F[32 + ng * 4], Bb + 16384u + off);
            }
        };

        ldfrag(0, fr[0]);
#pragma unroll
        for (int i = 0; i < NK * 4; i++) {
            if (i + 1 < NK * 4) ldfrag(i + 1, fr[(i + 1) & 1]);
            uint32_t (&F)[48] = fr[i & 1];
            // hi*hi
#pragma unroll
            for (int ng = 0; ng < 4; ng++)
#pragma unroll
                for (int mi = 0; mi < 2; mi++) {
                    mma16816(acc[mi][ng * 2],     &F[mi * 4], F[16 + ng * 4], F[16 + ng * 4 + 1]);
                    mma16816(acc[mi][ng * 2 + 1], &F[mi * 4], F[16 + ng * 4 + 2], F[16 + ng * 4 + 3]);
                }
            // lo*hi
#pragma unroll
            for (int ng = 0; ng < 4; ng++)
#pragma unroll
                for (int mi = 0; mi < 2; mi++) {
                    mma16816(acc[mi][ng * 2],     &F[8 + mi * 4], F[16 + ng * 4], F[16 + ng * 4 + 1]);
                    mma16816(acc[mi][ng * 2 + 1], &F[8 + mi * 4], F[16 + ng * 4 + 2], F[16 + ng * 4 + 3]);
                }
            // hi*lo
#pragma unroll
            for (int ng = 0; ng < 4; ng++)
#pragma unroll
                for (int mi = 0; mi < 2; mi++) {
                    mma16816(acc[mi][ng * 2],     &F[mi * 4], F[32 + ng * 4], F[32 + ng * 4 + 1]);
                    mma16816(acc[mi][ng * 2 + 1], &F[mi * 4], F[32 + ng * 4 + 2], F[32 + ng * 4 + 3]);
                }
        }
        __syncthreads();

        // ---------------- epilogue for this n-tile ----------------
        int n0 = nt * 128;
        int tg = lane >> 2;
        int tc = (lane & 3) * 2;
        if (EPI == 5) {
            float p[2][2] = {};
#pragma unroll
            for (int mi = 0; mi < 2; mi++)
#pragma unroll
                for (int ni = 0; ni < 8; ni++) {
                    int col = wn * 64 + ni * 8 + tc;
                    float b0 = bias[col], b1 = bias[col + 1];
                    float w20 = w2[col], w21 = w2[col + 1];
                    p[mi][0] += fmaxf(acc[mi][ni][0] + b0, 0.f) * w20 +
                                fmaxf(acc[mi][ni][1] + b1, 0.f) * w21;
                    p[mi][1] += fmaxf(acc[mi][ni][2] + b0, 0.f) * w20 +
                                fmaxf(acc[mi][ni][3] + b1, 0.f) * w21;
                }
#pragma unroll
            for (int mi = 0; mi < 2; mi++)
#pragma unroll
                for (int hf = 0; hf < 2; hf++) {
                    float v = p[mi][hf];
                    v += __shfl_xor_sync(~0u, v, 1);
                    v += __shfl_xor_sync(~0u, v, 2);
                    if ((lane & 3) == 0) red[wn][wm * 32 + mi * 16 + hf * 8 + tg] = v;
                }
            __syncthreads();
            if (tid < 128) {
                int row = m0 + tid;
                if (row < M) C[row] = red[0][tid] + red[1][tid] + pos[0];
            }
            continue;
        }

#pragma unroll
        for (int mi = 0; mi < 2; mi++) {
#pragma unroll
            for (int hf = 0; hf < 2; hf++) {
                int row = m0 + wm * 32 + mi * 16 + hf * 8 + tg;
                if (row >= M) continue;
#pragma unroll
                for (int ni = 0; ni < 8; ni++) {
                    int col = n0 + wn * 64 + ni * 8 + tc;
                    float v0 = acc[mi][ni][hf * 2 + 0];
                    float v1 = acc[mi][ni][hf * 2 + 1];
                    if (EPI == 0) {
                        *(float2*)&C[(long)row * Nfull + col] = make_float2(v0, v1);
                    } else if (EPI == 2) {
                        long pr = (long)(row % SEQ) * 128 + col;
                        v0 += bias[col] + pos[pr];
                        v1 += bias[col + 1] + pos[pr + 1];
                        *(float2*)&C[(long)row * Nfull + col] = make_float2(v0, v1);
                    } else if (EPI == 3) {
                        v0 += bias[col] + res[(long)row * Nfull + col];
                        v1 += bias[col + 1] + res[(long)row * Nfull + col + 1];
                        *(float2*)&C[(long)row * Nfull + col] = make_float2(v0, v1);
                        if (Chi) {
                            __nv_bfloat16 h0 = __float2bfloat16(v0), h1 = __float2bfloat16(v1);
                            __nv_bfloat16 hl[2] = {h0, h1};
                            __nv_bfloat16 ll[2] = {__float2bfloat16(v0 - __bfloat162float(h0)),
                                                   __float2bfloat16(v1 - __bfloat162float(h1))};
                            *(uint32_t*)&Chi[(long)row * Nfull + col] = *(uint32_t*)hl;
                            *(uint32_t*)&Clo[(long)row * Nfull + col] = *(uint32_t*)ll;
                        }
                    } else { // EPI 4
                        v0 += bias[col];
                        v1 += bias[col + 1];
                        v0 = 0.5f * v0 * (1.f + erff(v0 * 0.70710678118654752f));
                        v1 = 0.5f * v1 * (1.f + erff(v1 * 0.70710678118654752f));
                        __nv_bfloat16 h0 = __float2bfloat16(v0), h1 = __float2bfloat16(v1);
                        __nv_bfloat16 hl[2] = {h0, h1};
                        __nv_bfloat16 ll[2] = {__float2bfloat16(v0 - __bfloat162float(h0)),
                                               __float2bfloat16(v1 - __bfloat162float(h1))};
                        *(uint32_t*)&Chi[(long)row * Nfull + col] = *(uint32_t*)hl;
                        *(uint32_t*)&Clo[(long)row * Nfull + col] = *(uint32_t*)ll;
                    }
                }
            }
        }
    }
}

// =============== chunked GEMM for K=512 (ff2), 3-stage pipeline ==============
#define TILE_B 16384u
#define STAGE_B 65536u
#define NSTAGE 3

__global__ void __launch_bounds__(256, 1)
tgemmC(const __nv_bfloat16* __restrict__ Ah, const __nv_bfloat16* __restrict__ Al,
       const __nv_bfloat16* __restrict__ Bh, const __nv_bfloat16* __restrict__ Bl,
       const float* __restrict__ bias, const float* __restrict__ res,
       float* __restrict__ C, __nv_bfloat16* __restrict__ Chi,
       __nv_bfloat16* __restrict__ Clo, int M, int N, int K) {
    extern __shared__ char sm[];
    uint32_t sb = smem_u32(sm);
    int tid = threadIdx.x;
    int w = tid >> 5, lane = tid & 31;
    int wm = w & 3, wn = w >> 2;
    int m0 = blockIdx.y * 128, n0 = blockIdx.x * 128;
    int nk = K >> 6;

    float acc[2][8][4];
#pragma unroll
    for (int i = 0; i < 2; i++)
#pragma unroll
        for (int j = 0; j < 8; j++)
#pragma unroll
            for (int q = 0; q < 4; q++) acc[i][j][q] = 0.f;

    int rA[2], rB[4];
#pragma unroll
    for (int mi = 0; mi < 2; mi++) rA[mi] = wm * 32 + mi * 16 + (lane & 15);
#pragma unroll
    for (int ng = 0; ng < 4; ng++)
        rB[ng] = wn * 64 + ng * 16 + ((lane >> 4) << 3) + (lane & 7);
    int cA = lane >> 4;
    int cB = (lane >> 3) & 1;

    auto load_stage = [&](int c, int buf) {
#pragma unroll
        for (int it = 0; it < 16; it++) {
            int slot = it * 256 + tid;
            int t = it >> 2;
            int row = (slot >> 3) & 127;
            int chunk = slot & 7;
            const __nv_bfloat16* src = (t == 0) ? Ah : (t == 1) ? Al : (t == 2) ? Bh : Bl;
            long grow = (t < 2) ? (long)(m0 + row) : (long)(n0 + row);
            bool ok = (t < 2) ? (m0 + row < M) : true;
            if (!ok) grow = 0;
            const void* g = (const void*)(src + grow * K + ((long)c << 6) + chunk * 8);
            uint32_t saddr = sb + buf * STAGE_B + (uint32_t)t * TILE_B + row * 128 +
                             ((chunk ^ (row & 7)) << 4);
            cpasync16(saddr, g, ok ? 16u : 0u);
        }
        CP_COMMIT();
    };

#pragma unroll
    for (int p = 0; p < NSTAGE - 1; p++)
        if (p < nk) load_stage(p, p);

    uint32_t fr[2][48];
    for (int c = 0; c < nk; c++) {
        int nxt = c + NSTAGE - 1;
        if (nxt < nk) load_stage(nxt, nxt % NSTAGE);
        int allow = (nxt < nk ? nxt : nk - 1) - c;
        if (allow >= 2) CP_WAIT(2);
        else if (allow == 1) CP_WAIT(1);
        else CP_WAIT(0);
        __syncthreads();

        uint32_t st = sb + (c % NSTAGE) * STAGE_B;
        auto ldfrag = [&](int ks, uint32_t (&F)[48]) {
            int kc = ks * 2;
#pragma unroll
            for (int mi = 0; mi < 2; mi++) {
                int row = rA[mi];
                uint32_t off = row * 128 + ((((uint32_t)(kc + cA)) ^ (row & 7)) << 4);
                ldsm4(&F[mi * 4], st + off);
                ldsm4(&F[8 + mi * 4], st + TILE_B + off);
            }
#pragma unroll
            for (int ng = 0; ng < 4; ng++) {
                int row = rB[ng];
                uint32_t off = row * 128 + ((((uint32_t)(kc + cB)) ^ (row & 7)) << 4);
                ldsm4(&F[16 + ng * 4], st + 2 * TILE_B + off);
                ldsm4(&F[32 + ng * 4], st + 3 * TILE_B + off);
            }
        };
        ldfrag(0, fr[0]);
#pragma unroll
        for (int ks = 0; ks < 4; ks++) {
            if (ks < 3) ldfrag(ks + 1, fr[(ks + 1) & 1]);
            uint32_t (&F)[48] = fr[ks & 1];
#pragma unroll
            for (int ng = 0; ng < 4; ng++)
#pragma unroll
                for (int mi = 0; mi < 2; mi++) {
                    mma16816(acc[mi][ng * 2],     &F[mi * 4], F[16 + ng * 4], F[16 + ng * 4 + 1]);
                    mma16816(acc[mi][ng * 2 + 1], &F[mi * 4], F[16 + ng * 4 + 2], F[16 + ng * 4 + 3]);
                }
#pragma unroll
            for (int ng = 0; ng < 4; ng++)
#pragma unroll
                for (int mi = 0; mi < 2; mi++) {
                    mma16816(acc[mi][ng * 2],     &F[8 + mi * 4], F[16 + ng * 4], F[16 + ng * 4 + 1]);
                    mma16816(acc[mi][ng * 2 + 1], &F[8 + mi * 4], F[16 + ng * 4 + 2], F[16 + ng * 4 + 3]);
                }
#pragma unroll
            for (int ng = 0; ng < 4; ng++)
#pragma unroll
                for (int mi = 0; mi < 2; mi++) {
                    mma16816(acc[mi][ng * 2],     &F[mi * 4], F[32 + ng * 4], F[32 + ng * 4 + 1]);
                    mma16816(acc[mi][ng * 2 + 1], &F[mi * 4], F[32 + ng * 4 + 2], F[32 + ng * 4 + 3]);
                }
        }
        __syncthreads();
    }

    int tg = lane >> 2;
    int tc = (lane & 3) * 2;
#pragma unroll
    for (int mi = 0; mi < 2; mi++) {
#pragma unroll
        for (int hf = 0; hf < 2; hf++) {
            int row = m0 + wm * 32 + mi * 16 + hf * 8 + tg;
            if (row >= M) continue;
#pragma unroll
            for (int ni = 0; ni < 8; ni++) {
                int col = n0 + wn * 64 + ni * 8 + tc;
                float v0 = acc[mi][ni][hf * 2 + 0];
                float v1 = acc[mi][ni][hf * 2 + 1];
                v0 += bias[col] + res[(long)row * N + col];
                v1 += bias[col + 1] + res[(long)row * N + col + 1];
                *(float2*)&C[(long)row * N + col] = make_float2(v0, v1);
                if (Chi) {
                    __nv_bfloat16 h0 = __float2bfloat16(v0), h1 = __float2bfloat16(v1);
                    __nv_bfloat16 hl[2] = {h0, h1};
                    __nv_bfloat16 ll[2] = {__float2bfloat16(v0 - __bfloat162float(h0)),
                                           __float2bfloat16(v1 - __bfloat162float(h1))};
                    *(uint32_t*)&Chi[(long)row * N + col] = *(uint32_t*)hl;
                    *(uint32_t*)&Clo[(long)row * N + col] = *(uint32_t*)ll;
                }
            }
        }
    }
}

// ---------------- local windowed attention -----------------------------------
__global__ void attn_k(const float* __restrict__ qkv, __nv_bfloat16* __restrict__ ohi,
                       __nv_bfloat16* __restrict__ olo) {
    __shared__ float qs[S1][17];
    __shared__ float ks[3 * S1][17];
    __shared__ float vs[3 * S1][17];
    __shared__ float ps[8][192];
    int w = blockIdx.x;
    int bh = blockIdx.y;
    int b = bh >> 3, h = bh & 7;
    int tid = threadIdx.x;
    int jstart = (w > 0) ? 0 : S1;
    int jend = (w < S1 - 1) ? 3 * S1 : 2 * S1;
    long rb = (long)b * SEQ;

    for (int idx = tid; idx < S1 * DH; idx += 256) {
        int i = idx >> 4, d = idx & 15;
        qs[i][d] = qkv[(rb + w * S1 + i) * 384 + h * 16 + d] * 0.25f;
    }
    int cnt = jend - jstart;
    for (int idx = tid; idx < cnt * DH; idx += 256) {
        int j = jstart + (idx >> 4), d = idx & 15;
        long r = rb + (long)(w - 1) * S1 + j;
        ks[j][d] = qkv[r * 384 + 128 + h * 16 + d];
        vs[j][d] = qkv[r * 384 + 256 + h * 16 + d];
    }
    __syncthreads();

    int warp = tid >> 5, lane = tid & 31;
    for (int i = warp; i < S1; i += 8) {
        float ql[DH];
#pragma unroll
        for (int d = 0; d < DH; d++) ql[d] = qs[i][d];
        float sc[6];
        float mx = -1e30f;
        int c = 0;
        for (int j = jstart + lane; j < jend; j += 32) {
            float s = 0.f;
#pragma unroll
            for (int d = 0; d < DH; d++) s += ql[d] * ks[j][d];
            sc[c++] = s;
            mx = fmaxf(mx, s);
        }
#pragma unroll
        for (int off = 16; off; off >>= 1) mx = fmaxf(mx, __shfl_xor_sync(~0u, mx, off));
        float se = 0.f;
        c = 0;
        for (int j = jstart + lane; j < jend; j += 32) {
            float p = __expf(sc[c] - mx);
            sc[c++] = p;
            se += p;
        }
#pragma unroll
        for (int off = 16; off; off >>= 1) se += __shfl_xor_sync(~0u, se, off);
        float inv = 1.f / se;
        c = 0;
        for (int j = jstart + lane; j < jend; j += 32) ps[warp][j - jstart] = sc[c++] * inv;
        __syncwarp();
        int d = lane & 15, half = lane >> 4;
        float accv = 0.f;
        for (int jj = half; jj < cnt; jj += 2) accv += ps[warp][jj] * vs[jstart + jj][d];
        accv += __shfl_xor_sync(~0u, accv, 16);
        if (lane < 16) {
            long orow = (rb + w * S1 + i) * 128 + h * 16 + d;
            __nv_bfloat16 hv = __float2bfloat16(accv);
            ohi[orow] = hv;
            olo[orow] = __float2bfloat16(accv - __bfloat162float(hv));
        }
        __syncwarp();
    }
}

// ---------------- launch ------------------------------------------------------
extern "C" void kernel_launch(void* const* d_in, const int* in_sizes, int n_in,
                              void* d_out, int out_size) {
    const float* x      = (const float*)d_in[0];
    const float* conv_w = (const float*)d_in[1];
    const float* conv_b = (const float*)d_in[2];
    const float* lt_w   = (const float*)d_in[3];
    const float* lt_b   = (const float*)d_in[4];
    const float* pos    = (const float*)d_in[5];
    const float* ln1_s  = (const float*)d_in[6];
    const float* ln1_b  = (const float*)d_in[7];
    const float* wq     = (const float*)d_in[8];
    const float* wk     = (const float*)d_in[9];
    const float* wv     = (const float*)d_in[10];
    const float* wo     = (const float*)d_in[11];
    const float* wo_b   = (const float*)d_in[12];
    const float* ln2_s  = (const float*)d_in[13];
    const float* ln2_b  = (const float*)d_in[14];
    const float* ff_w1  = (const float*)d_in[15];
    const float* ff_b1  = (const float*)d_in[16];
    const float* ff_w2  = (const float*)d_in[17];
    const float* ff_b2  = (const float*)d_in[18];
    const float* pre_w1 = (const float*)d_in[19];
    const float* pre_b1 = (const float*)d_in[20];
    const float* pre_w2 = (const float*)d_in[21];
    const float* pre_b2 = (const float*)d_in[22];
    float* out = (float*)d_out;

    static bool attr_done = false;
    if (!attr_done) {
        cudaFuncSetAttribute(tgemmA<0,2>, cudaFuncAttributeMaxDynamicSharedMemorySize, SMEMSZ);
        cudaFuncSetAttribute(tgemmA<2,1>, cudaFuncAttributeMaxDynamicSharedMemorySize, SMEMSZ);
        cudaFuncSetAttribute(tgemmA<3,2>, cudaFuncAttributeMaxDynamicSharedMemorySize, SMEMSZ);
        cudaFuncSetAttribute(tgemmA<4,2>, cudaFuncAttributeMaxDynamicSharedMemorySize, SMEMSZ);
        cudaFuncSetAttribute(tgemmA<5,2>, cudaFuncAttributeMaxDynamicSharedMemorySize, SMEMSZ);
        cudaFuncSetAttribute(tgemmC, cudaFuncAttributeMaxDynamicSharedMemorySize, SMEMSZ);
        attr_done = true;
    }

    __nv_bfloat16 *phi, *plo, *lnhi, *lnlo, *atthi, *attlo, *ffhi, *fflo, *hhi, *hlo;
    __nv_bfloat16 *wlt_h, *wlt_l, *wqkv_h, *wqkv_l, *wo_h, *wo_l, *wf1_h, *wf1_l, *wf2_h, *wf2_l, *wp1_h, *wp1_l;
    float *h, *qkv;
    cudaGetSymbolAddress((void**)&phi, g_phi);     cudaGetSymbolAddress((void**)&plo, g_plo);
    cudaGetSymbolAddress((void**)&h, g_h);         cudaGetSymbolAddress((void**)&qkv, g_qkv);
    cudaGetSymbolAddress((void**)&lnhi, g_lnhi);   cudaGetSymbolAddress((void**)&lnlo, g_lnlo);
    cudaGetSymbolAddress((void**)&atthi, g_atthi); cudaGetSymbolAddress((void**)&attlo, g_attlo);
    cudaGetSymbolAddress((void**)&ffhi, g_ffhi);   cudaGetSymbolAddress((void**)&fflo, g_fflo);
    cudaGetSymbolAddress((void**)&hhi, g_hhi);     cudaGetSymbolAddress((void**)&hlo, g_hlo);
    cudaGetSymbolAddress((void**)&wlt_h, g_wlt_h); cudaGetSymbolAddress((void**)&wlt_l, g_wlt_l);
    cudaGetSymbolAddress((void**)&wqkv_h, g_wqkv_h); cudaGetSymbolAddress((void**)&wqkv_l, g_wqkv_l);
    cudaGetSymbolAddress((void**)&wo_h, g_wo_h);   cudaGetSymbolAddress((void**)&wo_l, g_wo_l);
    cudaGetSymbolAddress((void**)&wf1_h, g_wf1_h); cudaGetSymbolAddress((void**)&wf1_l, g_wf1_l);
    cudaGetSymbolAddress((void**)&wf2_h, g_wf2_h); cudaGetSymbolAddress((void**)&wf2_l, g_wf2_l);
    cudaGetSymbolAddress((void**)&wp1_h, g_wp1_h); cudaGetSymbolAddress((void**)&wp1_l, g_wp1_l);

    const int M = MROWS;
    int lnGrid = (M + 7) / 8;
    dim3 gA(1, MTILES);

    // 1: conv
    conv_k<<<(MROWS * 64 + 255) / 256, 256>>>(x, conv_w, conv_b, phi, plo);
    // 2: lt prep
    wprep_k<<<(128 * 64 + 255) / 256, 256>>>(lt_w, wlt_h, wlt_l, 49, 128, 64, 0, 0, 1);
    // 3: embed
    tgemmA<2,1><<<gA, 256, SMEMSZ>>>(phi, plo, wlt_h, wlt_l, lt_b, nullptr, pos,
                                     nullptr, h, nullptr, nullptr, M, 128, 1);
    // 4: qkv prep (all layers)
    qkvprep_k<<<(NLAYER * 384 * 128 + 255) / 256, 256>>>(wq, wk, wv, wqkv_h, wqkv_l);

    for (int i = 0; i < NLAYER; i++) {
        ln_k<<<lnGrid, 256>>>(h, ln1_s + i * 128, ln1_b + i * 128, lnhi, lnlo, M);
        // launch #6 on i==0: qkv GEMM (for ncu)
        tgemmA<0,2><<<gA, 256, SMEMSZ>>>(lnhi, lnlo,
            wqkv_h + (long)i * 49152, wqkv_l + (long)i * 49152,
            nullptr, nullptr, nullptr, nullptr, qkv, nullptr, nullptr, M, 384, 3);
        attn_k<<<dim3(S1, BATCH * HEADS), 256>>>(qkv, atthi, attlo);
        if (i == 0)
            wprep_k<<<(NLAYER * 128 * 128 + 255) / 256, 256>>>(wo, wo_h, wo_l, 128, 128, 128,
                                                               16384, 16384, NLAYER);
        tgemmA<3,2><<<gA, 256, SMEMSZ>>>(atthi, attlo,
            wo_h + (long)i * 16384, wo_l + (long)i * 16384,
            wo_b + i * 128, h, nullptr, nullptr, h, nullptr, nullptr, M, 128, 1);
        ln_k<<<lnGrid, 256>>>(h, ln2_s + i * 128, ln2_b + i * 128, lnhi, lnlo, M);
        if (i == 0)
            wprep_k<<<(NLAYER * 512 * 128 + 255) / 256, 256>>>(ff_w1, wf1_h, wf1_l, 128, 512, 128,
                                                               128 * 512, 512 * 128, NLAYER);
        tgemmA<4,2><<<gA, 256, SMEMSZ>>>(lnhi, lnlo,
            wf1_h + (long)i * 65536, wf1_l + (long)i * 65536,
            ff_b1 + i * 512, nullptr, nullptr, nullptr, nullptr, ffhi, fflo, M, 512, 4);
        if (i == 0)
            wprep_k<<<(NLAYER * 128 * 512 + 255) / 256, 256>>>(ff_w2, wf2_h, wf2_l, 512, 128, 512,
                                                               512 * 128, 128 * 512, NLAYER);
        bool last = (i == NLAYER - 1);
        tgemmC<<<dim3(1, MTILES), 256, SMEMSZ>>>(ffhi, fflo,
            wf2_h + (long)i * 65536, wf2_l + (long)i * 65536,
            ff_b2 + i * 128, h, h,
            last ? hhi : nullptr, last ? hlo : nullptr, M, 128, 512);
    }

    wprep_k<<<(128 * 128 + 255) / 256, 256>>>(pre_w1, wp1_h, wp1_l, 128, 128, 128, 0, 0, 1);
    tgemmA<5,2><<<gA, 256, SMEMSZ>>>(hhi, hlo, wp1_h, wp1_l, pre_b1, nullptr,
                                     pre_b2, pre_w2, out, nullptr, nullptr, M, 128, 1);
}

// round 6
// speedup vs baseline: 1.6594x; 1.2056x over previous
#include <cuda_runtime.h>
#include <cuda_fp16.h>
#include <cstdint>
#include <math.h>

#define BATCH 16
#define S1 61
#define SEQ 3721
#define DMODEL 128
#define HEADS 8
#define DH 16
#define NLAYER 4
#define FFDIM 512
#define PCH 49
#define MROWS (BATCH * SEQ) // 59536
#define MTILES ((MROWS + 127) / 128) // 466

// ---------------------------------------------------------------- scratch
__device__ __half g_p[MROWS * 64];
__device__ float  g_h[MROWS * 128];
__device__ __half g_ln[MROWS * 128];
__device__ float  g_qkv[(size_t)MROWS * 384];
__device__ __half g_att[MROWS * 128];
__device__ __half g_ff[(size_t)MROWS * 512];
__device__ __half g_hh[MROWS * 128];
__device__ __half g_wlt[128 * 64];
__device__ __half g_wqkv[NLAYER * 384 * 128];
__device__ __half g_wo[NLAYER * 128 * 128];
__device__ __half g_wf1[NLAYER * 512 * 128];
__device__ __half g_wf2[NLAYER * 128 * 512];
__device__ __half g_wp1[128 * 128];

// ---------------------------------------------------------------- helpers
__device__ __forceinline__ uint32_t smem_u32(const void* p) {
    uint32_t a;
    asm("{ .reg .u64 t; cvta.to.shared.u64 t, %1; cvt.u32.u64 %0, t; }" : "=r"(a) : "l"(p));
    return a;
}
__device__ __forceinline__ void ldsm4(uint32_t* r, uint32_t addr) {
    asm volatile("ldmatrix.sync.aligned.m8n8.x4.shared.b16 {%0,%1,%2,%3}, [%4];"
                 : "=r"(r[0]), "=r"(r[1]), "=r"(r[2]), "=r"(r[3]) : "r"(addr));
}
__device__ __forceinline__ void mma16816(float* c, const uint32_t* a, uint32_t b0, uint32_t b1) {
    asm volatile("mma.sync.aligned.m16n8k16.row.col.f32.f16.f16.f32 "
                 "{%0,%1,%2,%3}, {%4,%5,%6,%7}, {%8,%9}, {%0,%1,%2,%3};"
                 : "+f"(c[0]), "+f"(c[1]), "+f"(c[2]), "+f"(c[3])
                 : "r"(a[0]), "r"(a[1]), "r"(a[2]), "r"(a[3]), "r"(b0), "r"(b1));
}
__device__ __forceinline__ void cpasync16(uint32_t saddr, const void* g, uint32_t ssz) {
    asm volatile("cp.async.cg.shared.global [%0], [%1], 16, %2;"
                 :: "r"(saddr), "l"(g), "r"(ssz));
}
#define CP_COMMIT() asm volatile("cp.async.commit_group;" ::: "memory")
#define CP_WAIT(n)  asm volatile("cp.async.wait_group %0;" :: "n"(n) : "memory")

// ------------------------------------------- weight prep kernels
__global__ void wprep_k(const float* __restrict__ W, __half* __restrict__ o,
                        int K, int N, int Kp, long sstride, long dstride, int L) {
    long t = (long)blockIdx.x * blockDim.x + threadIdx.x;
    if (t >= (long)L * N * Kp) return;
    int l = (int)(t / (N * Kp));
    int r = (int)(t % (N * Kp));
    int n = r / Kp, kk = r % Kp;
    float v = (kk < K) ? W[l * sstride + (long)kk * N + n] : 0.f;
    o[l * dstride + r] = __float2half(v);
}

__global__ void qkvprep_k(const float* __restrict__ wq, const float* __restrict__ wk,
                          const float* __restrict__ wv, __half* __restrict__ o) {
    long t = (long)blockIdx.x * blockDim.x + threadIdx.x;
    if (t >= (long)NLAYER * 384 * 128) return;
    int l = (int)(t / (384 * 128));
    int r = (int)(t % (384 * 128));
    int n = r / 128, kk = r % 128;
    int s = n >> 7, nn = n & 127;
    const float* W = (s == 0 ? wq : s == 1 ? wk : wv) + (long)l * 16384;
    o[(long)l * 49152 + r] = __float2half(W[kk * 128 + nn]);
}

// ---------------- conv 7x7 'same' + relu -> fp16 [M,64] ----------------------
__global__ void conv_k(const float* __restrict__ x, const float* __restrict__ cw,
                       const float* __restrict__ cb, __half* __restrict__ p) {
    int t = blockIdx.x * blockDim.x + threadIdx.x;
    if (t >= MROWS * 64) return;
    int o = t & 63;
    float sum = 0.f;
    if (o < PCH) {
        int s = (t >> 6) % SEQ;
        int b = (t >> 6) / SEQ;
        int y = s / S1, xx = s % S1;
        const float* xb = x + (long)b * SEQ;
        const float* wo = cw + o * 49;
        sum = cb[o];
#pragma unroll
        for (int dy = 0; dy < 7; dy++) {
            int iy = y + dy - 3;
            if (iy < 0 || iy >= S1) continue;
#pragma unroll
            for (int dx = 0; dx < 7; dx++) {
                int ix = xx + dx - 3;
                if (ix < 0 || ix >= S1) continue;
                sum += xb[iy * S1 + ix] * wo[dy * 7 + dx];
            }
        }
        sum = fmaxf(sum, 0.f);
    }
    p[t] = __float2half(sum);
}

// ---------------- layernorm: warp per row -> fp16 ----------------------------
__global__ void ln_k(const float* __restrict__ x, const float* __restrict__ sc,
                     const float* __restrict__ bi, __half* __restrict__ o, int M) {
    int warp = (blockIdx.x * blockDim.x + threadIdx.x) >> 5;
    int lane = threadIdx.x & 31;
    if (warp >= M) return;
    float4 v = ((const float4*)(x + (long)warp * DMODEL))[lane];
    float sum = v.x + v.y + v.z + v.w;
#pragma unroll
    for (int off = 16; off; off >>= 1) sum += __shfl_xor_sync(~0u, sum, off);
    float mean = sum * (1.f / 128.f);
    float dx = v.x - mean, dy = v.y - mean, dz = v.z - mean, dw = v.w - mean;
    float vs = dx * dx + dy * dy + dz * dz + dw * dw;
#pragma unroll
    for (int off = 16; off; off >>= 1) vs += __shfl_xor_sync(~0u, vs, off);
    float inv = rsqrtf(vs * (1.f / 128.f) + 1e-5f);
    float4 s4 = ((const float4*)sc)[lane];
    float4 b4 = ((const float4*)bi)[lane];
    __half hv[4];
    hv[0] = __float2half(dx * inv * s4.x + b4.x);
    hv[1] = __float2half(dy * inv * s4.y + b4.y);
    hv[2] = __float2half(dz * inv * s4.z + b4.z);
    hv[3] = __float2half(dw * inv * s4.w + b4.w);
    *(uint2*)(o + (long)warp * 128 + lane * 4) = *(uint2*)hv;
}

// =============== A-resident fp16 GEMM (K<=128), N-loop inside ================
// C[M,NT*128] = A[M,K] @ Bt[NT*128,K]^T.  A resident in smem; B double-buffered.
// EPI: 0 fp32; 2 +bias+pos; 3 +bias+res -> fp32 (+opt fp16); 4 gelu(+bias)->fp16;
//      5 head row-reduce
template <int EPI, int NK>
__global__ void __launch_bounds__(256, 2)
tgemmA(const __half* __restrict__ A, const __half* __restrict__ B,
       const float* __restrict__ bias, const float* __restrict__ res,
       const float* __restrict__ pos, const float* __restrict__ w2,
       float* __restrict__ C, __half* __restrict__ Ch,
       int M, int Nfull, int NT) {
    extern __shared__ char sm[];
    __shared__ float red[2][128];
    uint32_t sb = smem_u32(sm);
    const int K = NK * 64;
    const uint32_t ABYTES = (uint32_t)NK * 16384u;
    int tid = threadIdx.x;
    int w = tid >> 5, lane = tid & 31;
    int wm = w & 3, wn = w >> 2;
    int m0 = blockIdx.y * 128;

    int rA[2], rB[4];
#pragma unroll
    for (int mi = 0; mi < 2; mi++) rA[mi] = wm * 32 + mi * 16 + (lane & 15);
#pragma unroll
    for (int ng = 0; ng < 4; ng++)
        rB[ng] = wn * 64 + ng * 16 + ((lane >> 4) << 3) + (lane & 7);
    int cA = lane >> 4;
    int cB = (lane >> 3) & 1;

    // ---- load A once (NK chunks of 16KB, swizzled) ----
#pragma unroll
    for (int t = 0; t < NK * 4; t++) {
        int slot = t * 256 + tid;
        int tile = slot >> 10;
        int idx = slot & 1023;
        int row = idx >> 3, c16 = idx & 7;
        long grow = m0 + row;
        bool ok = grow < M;
        if (!ok) grow = 0;
        cpasync16(sb + (uint32_t)tile * 16384u + row * 128 + (((uint32_t)c16 ^ (row & 7)) << 4),
                  A + grow * K + tile * 64 + c16 * 8, ok ? 16u : 0u);
    }
    CP_COMMIT();

    auto loadB = [&](int nt) {
#pragma unroll
        for (int t = 0; t < NK * 4; t++) {
            int slot = t * 256 + tid;
            int tile = slot >> 10;
            int idx = slot & 1023;
            int row = idx >> 3, c16 = idx & 7;
            long grow = (long)(nt * 128 + row);
            cpasync16(sb + ABYTES + (uint32_t)(nt & 1) * ABYTES + (uint32_t)tile * 16384u +
                          row * 128 + (((uint32_t)c16 ^ (row & 7)) << 4),
                      B + grow * K + tile * 64 + c16 * 8, 16u);
        }
        CP_COMMIT();
    };
    loadB(0);

    for (int nt = 0; nt < NT; nt++) {
        if (nt + 1 < NT) { loadB(nt + 1); CP_WAIT(1); }
        else             { CP_WAIT(0); }
        __syncthreads();

        float acc[2][8][4];
#pragma unroll
        for (int i = 0; i < 2; i++)
#pragma unroll
            for (int j = 0; j < 8; j++)
#pragma unroll
                for (int q = 0; q < 4; q++) acc[i][j][q] = 0.f;

        uint32_t Bbase = sb + ABYTES + (uint32_t)(nt & 1) * ABYTES;

#pragma unroll
        for (int i = 0; i < NK * 4; i++) {
            int chunk = i >> 2, ks = i & 3, kc = ks * 2;
            uint32_t Ab = sb + (uint32_t)chunk * 16384u;
            uint32_t Bb = Bbase + (uint32_t)chunk * 16384u;
            uint32_t fa[2][4], fb[4][4];
#pragma unroll
            for (int mi = 0; mi < 2; mi++) {
                int row = rA[mi];
                ldsm4(fa[mi], Ab + row * 128 + ((((uint32_t)(kc + cA)) ^ (row & 7)) << 4));
            }
#pragma unroll
            for (int ng = 0; ng < 4; ng++) {
                int row = rB[ng];
                ldsm4(fb[ng], Bb + row * 128 + ((((uint32_t)(kc + cB)) ^ (row & 7)) << 4));
            }
#pragma unroll
            for (int ng = 0; ng < 4; ng++)
#pragma unroll
                for (int mi = 0; mi < 2; mi++) {
                    mma16816(acc[mi][ng * 2],     fa[mi], fb[ng][0], fb[ng][1]);
                    mma16816(acc[mi][ng * 2 + 1], fa[mi], fb[ng][2], fb[ng][3]);
                }
        }
        __syncthreads();

        // ---------------- epilogue for this n-tile ----------------
        int n0 = nt * 128;
        int tg = lane >> 2;
        int tc = (lane & 3) * 2;
        if (EPI == 5) {
            float p[2][2] = {};
#pragma unroll
            for (int mi = 0; mi < 2; mi++)
#pragma unroll
                for (int ni = 0; ni < 8; ni++) {
                    int col = wn * 64 + ni * 8 + tc;
                    float b0 = bias[col], b1 = bias[col + 1];
                    float w20 = w2[col], w21 = w2[col + 1];
                    p[mi][0] += fmaxf(acc[mi][ni][0] + b0, 0.f) * w20 +
                                fmaxf(acc[mi][ni][1] + b1, 0.f) * w21;
                    p[mi][1] += fmaxf(acc[mi][ni][2] + b0, 0.f) * w20 +
                                fmaxf(acc[mi][ni][3] + b1, 0.f) * w21;
                }
#pragma unroll
            for (int mi = 0; mi < 2; mi++)
#pragma unroll
                for (int hf = 0; hf < 2; hf++) {
                    float v = p[mi][hf];
                    v += __shfl_xor_sync(~0u, v, 1);
                    v += __shfl_xor_sync(~0u, v, 2);
                    if ((lane & 3) == 0) red[wn][wm * 32 + mi * 16 + hf * 8 + tg] = v;
                }
            __syncthreads();
            if (tid < 128) {
                int row = m0 + tid;
                if (row < M) C[row] = red[0][tid] + red[1][tid] + pos[0];
            }
            continue;
        }

#pragma unroll
        for (int mi = 0; mi < 2; mi++) {
#pragma unroll
            for (int hf = 0; hf < 2; hf++) {
                int row = m0 + wm * 32 + mi * 16 + hf * 8 + tg;
                if (row >= M) continue;
#pragma unroll
                for (int ni = 0; ni < 8; ni++) {
                    int col = n0 + wn * 64 + ni * 8 + tc;
                    float v0 = acc[mi][ni][hf * 2 + 0];
                    float v1 = acc[mi][ni][hf * 2 + 1];
                    if (EPI == 0) {
                        *(float2*)&C[(long)row * Nfull + col] = make_float2(v0, v1);
                    } else if (EPI == 2) {
                        long pr = (long)(row % SEQ) * 128 + col;
                        v0 += bias[col] + pos[pr];
                        v1 += bias[col + 1] + pos[pr + 1];
                        *(float2*)&C[(long)row * Nfull + col] = make_float2(v0, v1);
                    } else if (EPI == 3) {
                        v0 += bias[col] + res[(long)row * Nfull + col];
                        v1 += bias[col + 1] + res[(long)row * Nfull + col + 1];
                        *(float2*)&C[(long)row * Nfull + col] = make_float2(v0, v1);
                        if (Ch) {
                            __half hl[2] = {__float2half(v0), __float2half(v1)};
                            *(uint32_t*)&Ch[(long)row * Nfull + col] = *(uint32_t*)hl;
                        }
                    } else { // EPI 4: gelu -> fp16
                        v0 += bias[col];
                        v1 += bias[col + 1];
                        v0 = 0.5f * v0 * (1.f + erff(v0 * 0.70710678118654752f));
                        v1 = 0.5f * v1 * (1.f + erff(v1 * 0.70710678118654752f));
                        __half hl[2] = {__float2half(v0), __float2half(v1)};
                        *(uint32_t*)&Ch[(long)row * Nfull + col] = *(uint32_t*)hl;
                    }
                }
            }
        }
    }
}

// =============== chunked fp16 GEMM for K=512 (ff2), 3-stage pipeline =========
#define CSTAGE_B 32768u

__global__ void __launch_bounds__(256, 2)
tgemmC(const __half* __restrict__ A, const __half* __restrict__ B,
       const float* __restrict__ bias, const float* __restrict__ res,
       float* __restrict__ C, __half* __restrict__ Ch, int M, int N, int K) {
    extern __shared__ char sm[];
    uint32_t sb = smem_u32(sm);
    int tid = threadIdx.x;
    int w = tid >> 5, lane = tid & 31;
    int wm = w & 3, wn = w >> 2;
    int m0 = blockIdx.y * 128, n0 = blockIdx.x * 128;
    int nk = K >> 6;

    float acc[2][8][4];
#pragma unroll
    for (int i = 0; i < 2; i++)
#pragma unroll
        for (int j = 0; j < 8; j++)
#pragma unroll
            for (int q = 0; q < 4; q++) acc[i][j][q] = 0.f;

    int rA[2], rB[4];
#pragma unroll
    for (int mi = 0; mi < 2; mi++) rA[mi] = wm * 32 + mi * 16 + (lane & 15);
#pragma unroll
    for (int ng = 0; ng < 4; ng++)
        rB[ng] = wn * 64 + ng * 16 + ((lane >> 4) << 3) + (lane & 7);
    int cA = lane >> 4;
    int cB = (lane >> 3) & 1;

    auto load_stage = [&](int c, int buf) {
#pragma unroll
        for (int it = 0; it < 8; it++) {
            int slot = it * 256 + tid;
            int t = it >> 2;                       // 0=A, 1=B
            int row = (slot >> 3) & 127;
            int chunk = slot & 7;
            const __half* src = t ? B : A;
            long grow = t ? (long)(n0 + row) : (long)(m0 + row);
            bool ok = t ? true : (m0 + row < M);
            if (!ok) grow = 0;
            const void* g = (const void*)(src + grow * K + ((long)c << 6) + chunk * 8);
            uint32_t saddr = sb + buf * CSTAGE_B + (uint32_t)t * 16384u + row * 128 +
                             ((chunk ^ (row & 7)) << 4);
            cpasync16(saddr, g, ok ? 16u : 0u);
        }
        CP_COMMIT();
    };

#pragma unroll
    for (int p = 0; p < 2; p++) load_stage(p, p);

    for (int c = 0; c < nk; c++) {
        int nxt = c + 2;
        if (nxt < nk) load_stage(nxt, nxt % 3);
        int allow = (nxt < nk ? nxt : nk - 1) - c;
        if (allow >= 2) CP_WAIT(2);
        else if (allow == 1) CP_WAIT(1);
        else CP_WAIT(0);
        __syncthreads();

        uint32_t st = sb + (c % 3) * CSTAGE_B;
#pragma unroll
        for (int ks = 0; ks < 4; ks++) {
            int kc = ks * 2;
            uint32_t fa[2][4], fb[4][4];
#pragma unroll
            for (int mi = 0; mi < 2; mi++) {
                int row = rA[mi];
                ldsm4(fa[mi], st + row * 128 + ((((uint32_t)(kc + cA)) ^ (row & 7)) << 4));
            }
#pragma unroll
            for (int ng = 0; ng < 4; ng++) {
                int row = rB[ng];
                ldsm4(fb[ng], st + 16384u + row * 128 + ((((uint32_t)(kc + cB)) ^ (row & 7)) << 4));
            }
#pragma unroll
            for (int ng = 0; ng < 4; ng++)
#pragma unroll
                for (int mi = 0; mi < 2; mi++) {
                    mma16816(acc[mi][ng * 2],     fa[mi], fb[ng][0], fb[ng][1]);
                    mma16816(acc[mi][ng * 2 + 1], fa[mi], fb[ng][2], fb[ng][3]);
                }
        }
        __syncthreads();
    }

    int tg = lane >> 2;
    int tc = (lane & 3) * 2;
#pragma unroll
    for (int mi = 0; mi < 2; mi++) {
#pragma unroll
        for (int hf = 0; hf < 2; hf++) {
            int row = m0 + wm * 32 + mi * 16 + hf * 8 + tg;
            if (row >= M) continue;
#pragma unroll
            for (int ni = 0; ni < 8; ni++) {
                int col = n0 + wn * 64 + ni * 8 + tc;
                float v0 = acc[mi][ni][hf * 2 + 0];
                float v1 = acc[mi][ni][hf * 2 + 1];
                v0 += bias[col] + res[(long)row * N + col];
                v1 += bias[col + 1] + res[(long)row * N + col + 1];
                *(float2*)&C[(long)row * N + col] = make_float2(v0, v1);
                if (Ch) {
                    __half hl[2] = {__float2half(v0), __float2half(v1)};
                    *(uint32_t*)&Ch[(long)row * N + col] = *(uint32_t*)hl;
                }
            }
        }
    }
}

// ---------------- local windowed attention -----------------------------------
__global__ void attn_k(const float* __restrict__ qkv, __half* __restrict__ o) {
    __shared__ float qs[S1][17];
    __shared__ float ks[3 * S1][17];
    __shared__ float vs[3 * S1][17];
    __shared__ float ps[8][192];
    int w = blockIdx.x;
    int bh = blockIdx.y;
    int b = bh >> 3, h = bh & 7;
    int tid = threadIdx.x;
    int jstart = (w > 0) ? 0 : S1;
    int jend = (w < S1 - 1) ? 3 * S1 : 2 * S1;
    long rb = (long)b * SEQ;

    for (int idx = tid; idx < S1 * DH; idx += 256) {
        int i = idx >> 4, d = idx & 15;
        qs[i][d] = qkv[(rb + w * S1 + i) * 384 + h * 16 + d] * 0.25f;
    }
    int cnt = jend - jstart;
    for (int idx = tid; idx < cnt * DH; idx += 256) {
        int j = jstart + (idx >> 4), d = idx & 15;
        long r = rb + (long)(w - 1) * S1 + j;
        ks[j][d] = qkv[r * 384 + 128 + h * 16 + d];
        vs[j][d] = qkv[r * 384 + 256 + h * 16 + d];
    }
    __syncthreads();

    int warp = tid >> 5, lane = tid & 31;
    for (int i = warp; i < S1; i += 8) {
        float ql[DH];
#pragma unroll
        for (int d = 0; d < DH; d++) ql[d] = qs[i][d];
        float sc[6];
        float mx = -1e30f;
        int c = 0;
        for (int j = jstart + lane; j < jend; j += 32) {
            float s = 0.f;
#pragma unroll
            for (int d = 0; d < DH; d++) s += ql[d] * ks[j][d];
            sc[c++] = s;
            mx = fmaxf(mx, s);
        }
#pragma unroll
        for (int off = 16; off; off >>= 1) mx = fmaxf(mx, __shfl_xor_sync(~0u, mx, off));
        float se = 0.f;
        c = 0;
        for (int j = jstart + lane; j < jend; j += 32) {
            float p = __expf(sc[c] - mx);
            sc[c++] = p;
            se += p;
        }
#pragma unroll
        for (int off = 16; off; off >>= 1) se += __shfl_xor_sync(~0u, se, off);
        float inv = 1.f / se;
        c = 0;
        for (int j = jstart + lane; j < jend; j += 32) ps[warp][j - jstart] = sc[c++] * inv;
        __syncwarp();
        int d = lane & 15, half = lane >> 4;
        float accv = 0.f;
        for (int jj = half; jj < cnt; jj += 2) accv += ps[warp][jj] * vs[jstart + jj][d];
        accv += __shfl_xor_sync(~0u, accv, 16);
        if (lane < 16) o[(rb + w * S1 + i) * 128 + h * 16 + d] = __float2half(accv);
        __syncwarp();
    }
}

// ---------------- launch ------------------------------------------------------
extern "C" void kernel_launch(void* const* d_in, const int* in_sizes, int n_in,
                              void* d_out, int out_size) {
    const float* x      = (const float*)d_in[0];
    const float* conv_w = (const float*)d_in[1];
    const float* conv_b = (const float*)d_in[2];
    const float* lt_w   = (const float*)d_in[3];
    const float* lt_b   = (const float*)d_in[4];
    const float* pos    = (const float*)d_in[5];
    const float* ln1_s  = (const float*)d_in[6];
    const float* ln1_b  = (const float*)d_in[7];
    const float* wq     = (const float*)d_in[8];
    const float* wk     = (const float*)d_in[9];
    const float* wv     = (const float*)d_in[10];
    const float* wo     = (const float*)d_in[11];
    const float* wo_b   = (const float*)d_in[12];
    const float* ln2_s  = (const float*)d_in[13];
    const float* ln2_b  = (const float*)d_in[14];
    const float* ff_w1  = (const float*)d_in[15];
    const float* ff_b1  = (const float*)d_in[16];
    const float* ff_w2  = (const float*)d_in[17];
    const float* ff_b2  = (const float*)d_in[18];
    const float* pre_w1 = (const float*)d_in[19];
    const float* pre_b1 = (const float*)d_in[20];
    const float* pre_w2 = (const float*)d_in[21];
    const float* pre_b2 = (const float*)d_in[22];
    float* out = (float*)d_out;

    static bool attr_done = false;
    if (!attr_done) {
        cudaFuncSetAttribute(tgemmA<0,2>, cudaFuncAttributeMaxDynamicSharedMemorySize, 98304);
        cudaFuncSetAttribute(tgemmA<2,1>, cudaFuncAttributeMaxDynamicSharedMemorySize, 49152);
        cudaFuncSetAttribute(tgemmA<3,2>, cudaFuncAttributeMaxDynamicSharedMemorySize, 98304);
        cudaFuncSetAttribute(tgemmA<4,2>, cudaFuncAttributeMaxDynamicSharedMemorySize, 98304);
        cudaFuncSetAttribute(tgemmA<5,2>, cudaFuncAttributeMaxDynamicSharedMemorySize, 98304);
        cudaFuncSetAttribute(tgemmC, cudaFuncAttributeMaxDynamicSharedMemorySize, 98304);
        attr_done = true;
    }

    __half *p, *lnb, *att, *ff, *hh, *wlt, *wqkv, *woh, *wf1, *wf2, *wp1;
    float *h, *qkv;
    cudaGetSymbolAddress((void**)&p, g_p);       cudaGetSymbolAddress((void**)&h, g_h);
    cudaGetSymbolAddress((void**)&lnb, g_ln);    cudaGetSymbolAddress((void**)&qkv, g_qkv);
    cudaGetSymbolAddress((void**)&att, g_att);   cudaGetSymbolAddress((void**)&ff, g_ff);
    cudaGetSymbolAddress((void**)&hh, g_hh);     cudaGetSymbolAddress((void**)&wlt, g_wlt);
    cudaGetSymbolAddress((void**)&wqkv, g_wqkv); cudaGetSymbolAddress((void**)&woh, g_wo);
    cudaGetSymbolAddress((void**)&wf1, g_wf1);   cudaGetSymbolAddress((void**)&wf2, g_wf2);
    cudaGetSymbolAddress((void**)&wp1, g_wp1);

    const int M = MROWS;
    int lnGrid = (M + 7) / 8;
    dim3 gA(1, MTILES);

    conv_k<<<(MROWS * 64 + 255) / 256, 256>>>(x, conv_w, conv_b, p);
    wprep_k<<<(128 * 64 + 255) / 256, 256>>>(lt_w, wlt, 49, 128, 64, 0, 0, 1);
    tgemmA<2,1><<<gA, 256, 49152>>>(p, wlt, lt_b, nullptr, pos, nullptr,
                                    h, nullptr, M, 128, 1);
    qkvprep_k<<<(NLAYER * 384 * 128 + 255) / 256, 256>>>(wq, wk, wv, wqkv);

    for (int i = 0; i < NLAYER; i++) {
        ln_k<<<lnGrid, 256>>>(h, ln1_s + i * 128, ln1_b + i * 128, lnb, M);
        tgemmA<0,2><<<gA, 256, 98304>>>(lnb, wqkv + (long)i * 49152,
            nullptr, nullptr, nullptr, nullptr, qkv, nullptr, M, 384, 3);
        attn_k<<<dim3(S1, BATCH * HEADS), 256>>>(qkv, att);
        if (i == 0)
            wprep_k<<<(NLAYER * 128 * 128 + 255) / 256, 256>>>(wo, woh, 128, 128, 128,
                                                               16384, 16384, NLAYER);
        tgemmA<3,2><<<gA, 256, 98304>>>(att, woh + (long)i * 16384,
            wo_b + i * 128, h, nullptr, nullptr, h, nullptr, M, 128, 1);
        ln_k<<<lnGrid, 256>>>(h, ln2_s + i * 128, ln2_b + i * 128, lnb, M);
        if (i == 0)
            wprep_k<<<(NLAYER * 512 * 128 + 255) / 256, 256>>>(ff_w1, wf1, 128, 512, 128,
                                                               128 * 512, 512 * 128, NLAYER);
        tgemmA<4,2><<<gA, 256, 98304>>>(lnb, wf1 + (long)i * 65536,
            ff_b1 + i * 512, nullptr, nullptr, nullptr, nullptr, ff, M, 512, 4);
        if (i == 0)
            wprep_k<<<(NLAYER * 128 * 512 + 255) / 256, 256>>>(ff_w2, wf2, 512, 128, 512,
                                                               512 * 128, 128 * 512, NLAYER);
        bool last = (i == NLAYER - 1);
        tgemmC<<<dim3(1, MTILES), 256, 98304>>>(ff, wf2 + (long)i * 65536,
            ff_b2 + i * 128, h, h, last ? hh : nullptr, M, 128, 512);
    }

    wprep_k<<<(128 * 128 + 255) / 256, 256>>>(pre_w1, wp1, 128, 128, 128, 0, 0, 1);
    tgemmA<5,2><<<gA, 256, 98304>>>(hh, wp1, pre_b1, nullptr, pre_b2, pre_w2,
                                    out, nullptr, M, 128, 1);
}